// round 8
// baseline (speedup 1.0000x reference)
#include <cuda_runtime.h>
#include <cuda_bf16.h>
#include <cstdint>
#include <math.h>

#define C_LEN 8192
#define Q_LEN 1024
#define D_DIM 1024

// ---------------- scratch (device globals) -----------------------------------
__device__ __align__(16) __nv_bfloat16 g_Hh[C_LEN * D_DIM];
__device__ __align__(16) __nv_bfloat16 g_Hl[C_LEN * D_DIM];
__device__ __align__(16) __nv_bfloat16 g_B1h[Q_LEN * D_DIM];
__device__ __align__(16) __nv_bfloat16 g_B1l[Q_LEN * D_DIM];
__device__ __align__(16) __nv_bfloat16 g_B2h[D_DIM * Q_LEN];
__device__ __align__(16) __nv_bfloat16 g_B2l[D_DIM * Q_LEN];
__device__ __align__(16) __nv_bfloat16 g_eh[C_LEN * Q_LEN];
__device__ __align__(16) __nv_bfloat16 g_el[C_LEN * Q_LEN];
__device__ __align__(16) float g_qterm[Q_LEN];
__device__ __align__(16) float g_cterm[C_LEN];
__device__ __align__(16) float g_bmax[C_LEN];
__device__ __align__(16) float g_colpart[64 * Q_LEN];
__device__ __align__(16) float g_rz[Q_LEN];
__device__ __align__(16) float g_w[C_LEN];
__device__ __align__(16) float g_hpart[64][D_DIM];
__device__ __align__(16) float g_hrow[D_DIM];

// ---------------- helpers -----------------------------------------------------
__device__ __forceinline__ uint32_t smem_u32(const void* p) {
    uint32_t a;
    asm("{ .reg .u64 t; cvta.to.shared.u64 t, %1; cvt.u32.u64 %0, t; }" : "=r"(a) : "l"(p));
    return a;
}
__device__ __forceinline__ uint32_t pack_lo_bf16x2(float l0, float l1) {
    uint32_t r;
    asm("cvt.rn.bf16x2.f32 %0, %1, %2;" : "=r"(r) : "f"(l1), "f"(l0));
    return r;
}
__device__ __forceinline__ void split4(float x, float y, float z, float w,
                                       uint32_t& h0, uint32_t& h1,
                                       uint32_t& l0, uint32_t& l1) {
    uint32_t bx = __float_as_uint(x), by = __float_as_uint(y);
    uint32_t bz = __float_as_uint(z), bw = __float_as_uint(w);
    h0 = __byte_perm(bx, by, 0x7632);
    h1 = __byte_perm(bz, bw, 0x7632);
    l0 = pack_lo_bf16x2(x - __uint_as_float(bx & 0xffff0000u),
                        y - __uint_as_float(by & 0xffff0000u));
    l1 = pack_lo_bf16x2(z - __uint_as_float(bz & 0xffff0000u),
                        w - __uint_as_float(bw & 0xffff0000u));
}
__device__ __forceinline__ void mma16816(float4& c, const uint32_t a[4],
                                         uint32_t b0, uint32_t b1) {
    asm volatile(
        "mma.sync.aligned.m16n8k16.row.col.f32.bf16.bf16.f32 "
        "{%0,%1,%2,%3}, {%4,%5,%6,%7}, {%8,%9}, {%0,%1,%2,%3};"
        : "+f"(c.x), "+f"(c.y), "+f"(c.z), "+f"(c.w)
        : "r"(a[0]), "r"(a[1]), "r"(a[2]), "r"(a[3]), "r"(b0), "r"(b1));
}
__device__ __forceinline__ void ldsm4(uint32_t d[4], uint32_t a) {
    asm volatile("ldmatrix.sync.aligned.m8n8.x4.shared.b16 {%0,%1,%2,%3}, [%4];"
                 : "=r"(d[0]), "=r"(d[1]), "=r"(d[2]), "=r"(d[3]) : "r"(a));
}
#define CP_ASYNC(d, s) asm volatile("cp.async.ca.shared.global [%0], [%1], 16;" :: "r"(d), "l"(s) : "memory")
#define CP_COMMIT()    asm volatile("cp.async.commit_group;" ::: "memory")
#define CP_WAIT2()     asm volatile("cp.async.wait_group 2;" ::: "memory")

// ---------------- fused stats: rowstat (blocks 0..8191) + qterm (8192..9215) --
__global__ void k_stats(const float* __restrict__ H, const float* __restrict__ U,
                        const float* __restrict__ wq, const float* __restrict__ bq,
                        const float* __restrict__ wc, const float* __restrict__ bc) {
    const int t = threadIdx.x;
    __shared__ float sp[8], sm2[8];
    if (blockIdx.x < C_LEN) {
        const int c = blockIdx.x;
        float4 h = ((const float4*)H)[c * 256 + t];
        float4 w = ((const float4*)wc)[t];
        float p = h.x * w.x + h.y * w.y + h.z * w.z + h.w * w.w;
        float m = fmaxf(fmaxf(h.x, h.y), fmaxf(h.z, h.w));
#pragma unroll
        for (int o = 16; o; o >>= 1) {
            p += __shfl_down_sync(0xffffffffu, p, o);
            m = fmaxf(m, __shfl_down_sync(0xffffffffu, m, o));
        }
        if ((t & 31) == 0) { sp[t >> 5] = p; sm2[t >> 5] = m; }
        __syncthreads();
        if (t == 0) {
            float pp = sp[0], mm = sm2[0];
#pragma unroll
            for (int i = 1; i < 8; ++i) { pp += sp[i]; mm = fmaxf(mm, sm2[i]); }
            g_cterm[c] = pp + bc[0];
            g_bmax[c] = mm;
        }
    } else {
        const int n = blockIdx.x - C_LEN;
        float4 u = ((const float4*)U)[n * 256 + t];
        float4 w = ((const float4*)wq)[t];
        float p = u.x * w.x + u.y * w.y + u.z * w.z + u.w * w.w;
#pragma unroll
        for (int o = 16; o; o >>= 1) p += __shfl_down_sync(0xffffffffu, p, o);
        if ((t & 31) == 0) sp[t >> 5] = p;
        __syncthreads();
        if (t == 0) {
            float s = sp[0];
#pragma unroll
            for (int i = 1; i < 8; ++i) s += sp[i];
            g_qterm[n] = s + bq[0];
        }
    }
}

// ---------------- prep: split H  (8192 blocks x 256 thr x 4 elts = 8.39M) ----
__global__ void k_prep_h(const float* __restrict__ H) {
    const int i = (blockIdx.x * 256 + threadIdx.x) * 4;
    float4 a = *(const float4*)(H + i);
    uint32_t h0, h1, l0, l1;
    split4(a.x, a.y, a.z, a.w, h0, h1, l0, l1);
    *(uint2*)((uint16_t*)g_Hh + i) = make_uint2(h0, h1);
    *(uint2*)((uint16_t*)g_Hl + i) = make_uint2(l0, l1);
}

// ---------------- prep: split (U * wqc) ----------------------------------------
__global__ void k_prep_uw(const float* __restrict__ U, const float* __restrict__ wqc) {
    const int q = blockIdx.x, t = threadIdx.x;
    const int i = q * 1024 + t * 4;
    float4 a = *(const float4*)(U + i);
    float4 w = ((const float4*)wqc)[t];
    a.x *= w.x; a.y *= w.y; a.z *= w.z; a.w *= w.w;
    uint32_t h0, h1, l0, l1;
    split4(a.x, a.y, a.z, a.w, h0, h1, l0, l1);
    *(uint2*)((uint16_t*)g_B1h + i) = make_uint2(h0, h1);
    *(uint2*)((uint16_t*)g_B1l + i) = make_uint2(l0, l1);
}

// ---------------- prep: transpose+split (U * rz)^T -----------------------------
__global__ void k_prep_ut(const float* __restrict__ U) {
    __shared__ float t[32][33];
    const int tx = threadIdx.x & 31, ty = threadIdx.x >> 5;
    const int d0 = blockIdx.x * 32, q0 = blockIdx.y * 32;
#pragma unroll
    for (int i = 0; i < 4; ++i)
        t[ty + 8 * i][tx] = U[(size_t)(q0 + ty + 8 * i) * 1024 + d0 + tx];
    __syncthreads();
#pragma unroll
    for (int i = 0; i < 4; ++i) {
        const int d = d0 + ty + 8 * i;
        const int q = q0 + tx;
        const float v = t[tx][ty + 8 * i] * g_rz[q];
        const uint32_t b = __float_as_uint(v);
        ((uint16_t*)g_B2h)[(size_t)d * 1024 + q] = (uint16_t)(b >> 16);
        const float l = v - __uint_as_float(b & 0xffff0000u);
        ((__nv_bfloat16*)g_B2l)[(size_t)d * 1024 + q] = __float2bfloat16(l);
    }
}

// -------- GEMM: 4-stage cp.async, K=16/stage, 4 warps 64x64, 2 CTA/SM ---------
// stage = Ah(4K) | Al(4K) | Bh(4K) | Bl(4K) = 16KB, 4 stages = 64KB
#define TS    16384u
#define O_AL  4096u
#define O_BH  8192u
#define O_BL  12288u
#define NSTG  4

// 128 threads: each thread issues 2 chunk-units per array (256 units of 16B each)
__device__ __forceinline__ void fill_stage(uint32_t sbuf,
                                           const __nv_bfloat16* Ah, const __nv_bfloat16* Al,
                                           const __nv_bfloat16* Bh, const __nv_bfloat16* Bl,
                                           int m0, int n0, int k0, int t) {
#pragma unroll
    for (int u = 0; u < 2; ++u) {
        const int row = (t >> 1) + u * 64, ch = t & 1;
        const int chs = ch ^ ((row >> 2) & 1);
        const uint32_t d = sbuf + (uint32_t)(row * 32 + chs * 16);
        const size_t oa = (size_t)(m0 + row) * 1024 + k0 + ch * 8;
        const size_t ob = (size_t)(n0 + row) * 1024 + k0 + ch * 8;
        CP_ASYNC(d,        Ah + oa);
        CP_ASYNC(d + O_AL, Al + oa);
        CP_ASYNC(d + O_BH, Bh + ob);
        CP_ASYNC(d + O_BL, Bl + ob);
    }
}

template <int PASS>
__global__ __launch_bounds__(128, 2)
void k_mma(const __nv_bfloat16* __restrict__ Ah, const __nv_bfloat16* __restrict__ Al,
           const __nv_bfloat16* __restrict__ Bh, const __nv_bfloat16* __restrict__ Bl,
           const float* __restrict__ bqc, float* __restrict__ out) {
    extern __shared__ char sm[];
    const uint32_t sb = smem_u32(sm);
    const int tid = threadIdx.x;
    const int lane = tid & 31, wid = tid >> 5;
    const int wm = wid & 1, wn = wid >> 1;           // 2 x 2 warps, warp tile 64x64
    const int g = lane >> 2, tq = lane & 3;
    const int m0 = blockIdx.y * 128, n0 = blockIdx.x * 128;
    const int lr = lane & 15, lc = lane >> 4;

    float4 acc[4][8];
#pragma unroll
    for (int i = 0; i < 4; ++i)
#pragma unroll
        for (int j = 0; j < 8; ++j) acc[i][j] = make_float4(0.f, 0.f, 0.f, 0.f);

#pragma unroll
    for (int s = 0; s < 3; ++s) {
        fill_stage(sb + s * TS, Ah, Al, Bh, Bl, m0, n0, s * 16, tid);
        CP_COMMIT();
    }

    for (int s = 0; s < 64; ++s) {
        CP_WAIT2();
        __syncthreads();
        const uint32_t buf = sb + (uint32_t)(s & 3) * TS;

        uint32_t ah[4][4], al[4][4], bh[4][4], bl[4][4];
#pragma unroll
        for (int mt = 0; mt < 4; ++mt) {
            const int row = wm * 64 + mt * 16 + lr;
            const uint32_t off = (uint32_t)(row * 32 + ((lc ^ ((row >> 2) & 1)) * 16));
            ldsm4(ah[mt], buf + off);
            ldsm4(al[mt], buf + O_AL + off);
        }
#pragma unroll
        for (int nb = 0; nb < 4; ++nb) {
            const int row = wn * 64 + nb * 16 + lr;
            const uint32_t off = (uint32_t)(row * 32 + ((lc ^ ((row >> 2) & 1)) * 16));
            ldsm4(bh[nb], buf + O_BH + off);
            ldsm4(bl[nb], buf + O_BL + off);
        }
#pragma unroll
        for (int mt = 0; mt < 4; ++mt)
#pragma unroll
            for (int nt = 0; nt < 8; ++nt) {
                const int nb = nt >> 1, p = nt & 1;
                mma16816(acc[mt][nt], ah[mt], bh[nb][p], bh[nb][p + 2]);
                mma16816(acc[mt][nt], ah[mt], bl[nb][p], bl[nb][p + 2]);
                mma16816(acc[mt][nt], al[mt], bh[nb][p], bh[nb][p + 2]);
            }

        if (s < 61)
            fill_stage(sb + (uint32_t)((s + 3) & 3) * TS, Ah, Al, Bh, Bl,
                       m0, n0, (s + 3) * 16, tid);
        CP_COMMIT();
    }
    __syncthreads();

    if (PASS == 1) {
        const float bq = bqc[0];
        float* s_cp = (float*)sm;  // [2][128] overlay
        float cs[8][2];
#pragma unroll
        for (int nt = 0; nt < 8; ++nt) { cs[nt][0] = 0.f; cs[nt][1] = 0.f; }
#pragma unroll
        for (int mt = 0; mt < 4; ++mt) {
            const int row = m0 + wm * 64 + mt * 16 + g;
            const float ct0 = g_cterm[row], ct1 = g_cterm[row + 8];
#pragma unroll
            for (int nt = 0; nt < 8; ++nt) {
                const int col = n0 + wn * 64 + nt * 8 + tq * 2;
                const float q0 = g_qterm[col] + bq, q1 = g_qterm[col + 1] + bq;
                const float4 c = acc[mt][nt];
                const float e00 = __expf(c.x + ct0 + q0), e01 = __expf(c.y + ct0 + q1);
                const float e10 = __expf(c.z + ct1 + q0), e11 = __expf(c.w + ct1 + q1);
                uint32_t h0, h1, l0, l1;
                split4(e00, e01, e10, e11, h0, h1, l0, l1);
                const size_t o0 = (size_t)row * 1024 + col;
                const size_t o1 = (size_t)(row + 8) * 1024 + col;
                *(uint32_t*)((uint16_t*)g_eh + o0) = h0;
                *(uint32_t*)((uint16_t*)g_el + o0) = l0;
                *(uint32_t*)((uint16_t*)g_eh + o1) = h1;
                *(uint32_t*)((uint16_t*)g_el + o1) = l1;
                cs[nt][0] += e00 + e10;
                cs[nt][1] += e01 + e11;
            }
        }
#pragma unroll
        for (int nt = 0; nt < 8; ++nt)
#pragma unroll
            for (int o = 4; o < 32; o <<= 1) {
                cs[nt][0] += __shfl_xor_sync(0xffffffffu, cs[nt][0], o);
                cs[nt][1] += __shfl_xor_sync(0xffffffffu, cs[nt][1], o);
            }
        if (g == 0) {
#pragma unroll
            for (int nt = 0; nt < 8; ++nt) {
                const int col = wn * 64 + nt * 8 + tq * 2;
                s_cp[wm * 128 + col] = cs[nt][0];
                s_cp[wm * 128 + col + 1] = cs[nt][1];
            }
        }
        __syncthreads();
        if (tid < 128) {
            const float v = s_cp[tid] + s_cp[128 + tid];
            g_colpart[blockIdx.y * 1024 + n0 + tid] = v;
        }
    } else {
#pragma unroll
        for (int mt = 0; mt < 4; ++mt) {
            const int row = m0 + wm * 64 + mt * 16 + g;
#pragma unroll
            for (int nt = 0; nt < 8; ++nt) {
                const int col = n0 + wn * 64 + nt * 8 + tq * 2;
                const float4 c = acc[mt][nt];
                *(float2*)(out + (size_t)row * 1024 + col) = make_float2(c.x, c.y);
                *(float2*)(out + (size_t)(row + 8) * 1024 + col) = make_float2(c.z, c.w);
            }
        }
    }
}

// ---------------- Z_q reduction -------------------------------------------------
__global__ void k_colfin() {
    const int q = blockIdx.x * 256 + threadIdx.x;
    float s = 0.f;
#pragma unroll
    for (int i = 0; i < 64; ++i) s += g_colpart[i * 1024 + q];
    g_rz[q] = 1.f / s;
}

// ---------------- c2q softmax ---------------------------------------------------
__global__ void k_c2q() {
    const int t = threadIdx.x;
    const int lane = t & 31, wid = t >> 5;
    __shared__ float sred[32];
    __shared__ float sbc[2];
    float m = -1e30f;
    for (int c = t; c < C_LEN; c += 1024) m = fmaxf(m, g_bmax[c]);
#pragma unroll
    for (int o = 16; o; o >>= 1) m = fmaxf(m, __shfl_xor_sync(0xffffffffu, m, o));
    if (lane == 0) sred[wid] = m;
    __syncthreads();
    if (t < 32) {
        float v = sred[t];
#pragma unroll
        for (int o = 16; o; o >>= 1) v = fmaxf(v, __shfl_xor_sync(0xffffffffu, v, o));
        if (t == 0) sbc[0] = v;
    }
    __syncthreads();
    const float mm = sbc[0];
    float z = 0.f;
    for (int c = t; c < C_LEN; c += 1024) z += expf(g_bmax[c] - mm);
#pragma unroll
    for (int o = 16; o; o >>= 1) z += __shfl_xor_sync(0xffffffffu, z, o);
    __syncthreads();
    if (lane == 0) sred[wid] = z;
    __syncthreads();
    if (t < 32) {
        float v = sred[t];
#pragma unroll
        for (int o = 16; o; o >>= 1) v += __shfl_xor_sync(0xffffffffu, v, o);
        if (t == 0) sbc[1] = v;
    }
    __syncthreads();
    const float rz = 1.f / sbc[1];
    for (int c = t; c < C_LEN; c += 1024) g_w[c] = expf(g_bmax[c] - mm) * rz;
}

// ---------------- weighted column sum of H ---------------------------------------
__global__ void k_hpart(const float* __restrict__ H) {
    const int chunk = blockIdx.x, t = threadIdx.x;
    float a0 = 0.f, a1 = 0.f, a2 = 0.f, a3 = 0.f;
    const int c0 = chunk * 128;
    for (int c = c0; c < c0 + 128; ++c) {
        const float wv = g_w[c];
        const float* hr = H + (size_t)c * 1024;
        a0 = fmaf(wv, hr[t], a0);
        a1 = fmaf(wv, hr[t + 256], a1);
        a2 = fmaf(wv, hr[t + 512], a2);
        a3 = fmaf(wv, hr[t + 768], a3);
    }
    g_hpart[chunk][t] = a0;
    g_hpart[chunk][t + 256] = a1;
    g_hpart[chunk][t + 512] = a2;
    g_hpart[chunk][t + 768] = a3;
}

__global__ void k_hred() {
    const int d = blockIdx.x * 256 + threadIdx.x;
    float s = 0.f;
#pragma unroll
    for (int i = 0; i < 64; ++i) s += g_hpart[i][d];
    g_hrow[d] = s;
}

__global__ void k_bcast(float* __restrict__ out) {
    const float4 v = ((const float4*)g_hrow)[threadIdx.x];
    ((float4*)(out + (size_t)C_LEN * D_DIM))[blockIdx.x * 256 + threadIdx.x] = v;
}

// ---------------- launch ----------------------------------------------------------
extern "C" void kernel_launch(void* const* d_in, const int* in_sizes, int n_in,
                              void* d_out, int out_size) {
    const float* H   = (const float*)d_in[0];
    const float* U   = (const float*)d_in[1];
    const float* wq  = (const float*)d_in[2];
    const float* bq  = (const float*)d_in[3];
    const float* wc  = (const float*)d_in[4];
    const float* bc  = (const float*)d_in[5];
    const float* wqc = (const float*)d_in[6];
    const float* bqc = (const float*)d_in[7];
    float* out = (float*)d_out;

    static bool s_attr = false;
    if (!s_attr) {
        cudaFuncSetAttribute(k_mma<1>, cudaFuncAttributeMaxDynamicSharedMemorySize, NSTG * TS);
        cudaFuncSetAttribute(k_mma<2>, cudaFuncAttributeMaxDynamicSharedMemorySize, NSTG * TS);
        s_attr = true;
    }

    void *hh, *hl, *b1h, *b1l, *eh, *el, *b2h, *b2l;
    cudaGetSymbolAddress(&hh, g_Hh);
    cudaGetSymbolAddress(&hl, g_Hl);
    cudaGetSymbolAddress(&b1h, g_B1h);
    cudaGetSymbolAddress(&b1l, g_B1l);
    cudaGetSymbolAddress(&eh, g_eh);
    cudaGetSymbolAddress(&el, g_el);
    cudaGetSymbolAddress(&b2h, g_B2h);
    cudaGetSymbolAddress(&b2l, g_B2l);

    k_stats<<<C_LEN + Q_LEN, 256>>>(H, U, wq, bq, wc, bc);
    k_prep_h<<<C_LEN * D_DIM / 1024, 256>>>(H);
    k_prep_uw<<<Q_LEN, 256>>>(U, wqc);
    k_mma<1><<<dim3(8, 64), 128, NSTG * TS>>>((const __nv_bfloat16*)hh, (const __nv_bfloat16*)hl,
                                              (const __nv_bfloat16*)b1h, (const __nv_bfloat16*)b1l,
                                              bqc, nullptr);
    k_colfin<<<4, 256>>>();
    k_prep_ut<<<dim3(32, 32), 256>>>(U);
    k_mma<2><<<dim3(8, 64), 128, NSTG * TS>>>((const __nv_bfloat16*)eh, (const __nv_bfloat16*)el,
                                              (const __nv_bfloat16*)b2h, (const __nv_bfloat16*)b2l,
                                              bqc, out);
    k_c2q<<<1, 1024>>>();
    k_hpart<<<64, 256>>>(H);
    k_hred<<<4, 256>>>();
    k_bcast<<<C_LEN, 256>>>(out);
}

// round 9
// speedup vs baseline: 1.1020x; 1.1020x over previous
#include <cuda_runtime.h>
#include <cuda_bf16.h>
#include <cstdint>
#include <math.h>

#define C_LEN 8192
#define Q_LEN 1024
#define D_DIM 1024

// ---------------- scratch (device globals) -----------------------------------
__device__ __align__(16) __nv_bfloat16 g_Hh[C_LEN * D_DIM];
__device__ __align__(16) __nv_bfloat16 g_Hl[C_LEN * D_DIM];
__device__ __align__(16) __nv_bfloat16 g_B1h[Q_LEN * D_DIM];
__device__ __align__(16) __nv_bfloat16 g_B1l[Q_LEN * D_DIM];
__device__ __align__(16) __nv_bfloat16 g_B2h[D_DIM * Q_LEN];
__device__ __align__(16) __nv_bfloat16 g_B2l[D_DIM * Q_LEN];
__device__ __align__(16) __nv_bfloat16 g_eh[C_LEN * Q_LEN];
__device__ __align__(16) __nv_bfloat16 g_el[C_LEN * Q_LEN];
__device__ __align__(16) float g_qterm[Q_LEN];
__device__ __align__(16) float g_cterm[C_LEN];
__device__ __align__(16) float g_bmax[C_LEN];
__device__ __align__(16) float g_colpart[64 * Q_LEN];
__device__ __align__(16) float g_rz[Q_LEN];
__device__ __align__(16) float g_w[C_LEN];
__device__ __align__(16) float g_hpart[64][D_DIM];
__device__ __align__(16) float g_hrow[D_DIM];

// ---------------- helpers -----------------------------------------------------
__device__ __forceinline__ uint32_t smem_u32(const void* p) {
    uint32_t a;
    asm("{ .reg .u64 t; cvta.to.shared.u64 t, %1; cvt.u32.u64 %0, t; }" : "=r"(a) : "l"(p));
    return a;
}
__device__ __forceinline__ uint32_t pack_lo_bf16x2(float l0, float l1) {
    uint32_t r;
    asm("cvt.rn.bf16x2.f32 %0, %1, %2;" : "=r"(r) : "f"(l1), "f"(l0));
    return r;
}
__device__ __forceinline__ void split4(float x, float y, float z, float w,
                                       uint32_t& h0, uint32_t& h1,
                                       uint32_t& l0, uint32_t& l1) {
    uint32_t bx = __float_as_uint(x), by = __float_as_uint(y);
    uint32_t bz = __float_as_uint(z), bw = __float_as_uint(w);
    h0 = __byte_perm(bx, by, 0x7632);
    h1 = __byte_perm(bz, bw, 0x7632);
    l0 = pack_lo_bf16x2(x - __uint_as_float(bx & 0xffff0000u),
                        y - __uint_as_float(by & 0xffff0000u));
    l1 = pack_lo_bf16x2(z - __uint_as_float(bz & 0xffff0000u),
                        w - __uint_as_float(bw & 0xffff0000u));
}
__device__ __forceinline__ void mma16816(float4& c, const uint32_t a[4],
                                         uint32_t b0, uint32_t b1) {
    asm volatile(
        "mma.sync.aligned.m16n8k16.row.col.f32.bf16.bf16.f32 "
        "{%0,%1,%2,%3}, {%4,%5,%6,%7}, {%8,%9}, {%0,%1,%2,%3};"
        : "+f"(c.x), "+f"(c.y), "+f"(c.z), "+f"(c.w)
        : "r"(a[0]), "r"(a[1]), "r"(a[2]), "r"(a[3]), "r"(b0), "r"(b1));
}
__device__ __forceinline__ void ldsm4(uint32_t d[4], uint32_t a) {
    asm volatile("ldmatrix.sync.aligned.m8n8.x4.shared.b16 {%0,%1,%2,%3}, [%4];"
                 : "=r"(d[0]), "=r"(d[1]), "=r"(d[2]), "=r"(d[3]) : "r"(a));
}
#define CP_ASYNC(d, s) asm volatile("cp.async.ca.shared.global [%0], [%1], 16;" :: "r"(d), "l"(s) : "memory")
#define CP_COMMIT()    asm volatile("cp.async.commit_group;" ::: "memory")
#define CP_WAIT1()     asm volatile("cp.async.wait_group 1;" ::: "memory")

// ---------------- fused stats: rowstat (blocks 0..8191) + qterm (8192..9215) --
__global__ void k_stats(const float* __restrict__ H, const float* __restrict__ U,
                        const float* __restrict__ wq, const float* __restrict__ bq,
                        const float* __restrict__ wc, const float* __restrict__ bc) {
    const int t = threadIdx.x;
    __shared__ float sp[8], sm2[8];
    if (blockIdx.x < C_LEN) {
        const int c = blockIdx.x;
        float4 h = ((const float4*)H)[c * 256 + t];
        float4 w = ((const float4*)wc)[t];
        float p = h.x * w.x + h.y * w.y + h.z * w.z + h.w * w.w;
        float m = fmaxf(fmaxf(h.x, h.y), fmaxf(h.z, h.w));
#pragma unroll
        for (int o = 16; o; o >>= 1) {
            p += __shfl_down_sync(0xffffffffu, p, o);
            m = fmaxf(m, __shfl_down_sync(0xffffffffu, m, o));
        }
        if ((t & 31) == 0) { sp[t >> 5] = p; sm2[t >> 5] = m; }
        __syncthreads();
        if (t == 0) {
            float pp = sp[0], mm = sm2[0];
#pragma unroll
            for (int i = 1; i < 8; ++i) { pp += sp[i]; mm = fmaxf(mm, sm2[i]); }
            g_cterm[c] = pp + bc[0];
            g_bmax[c] = mm;
        }
    } else {
        const int n = blockIdx.x - C_LEN;
        float4 u = ((const float4*)U)[n * 256 + t];
        float4 w = ((const float4*)wq)[t];
        float p = u.x * w.x + u.y * w.y + u.z * w.z + u.w * w.w;
#pragma unroll
        for (int o = 16; o; o >>= 1) p += __shfl_down_sync(0xffffffffu, p, o);
        if ((t & 31) == 0) sp[t >> 5] = p;
        __syncthreads();
        if (t == 0) {
            float s = sp[0];
#pragma unroll
            for (int i = 1; i < 8; ++i) s += sp[i];
            g_qterm[n] = s + bq[0];
        }
    }
}

// ---------------- prep: split H  (8192 blocks x 256 thr x 4 elts = 8.39M) ----
__global__ void k_prep_h(const float* __restrict__ H) {
    const int i = (blockIdx.x * 256 + threadIdx.x) * 4;
    float4 a = *(const float4*)(H + i);
    uint32_t h0, h1, l0, l1;
    split4(a.x, a.y, a.z, a.w, h0, h1, l0, l1);
    *(uint2*)((uint16_t*)g_Hh + i) = make_uint2(h0, h1);
    *(uint2*)((uint16_t*)g_Hl + i) = make_uint2(l0, l1);
}

// ---------------- prep: split (U * wqc) ----------------------------------------
__global__ void k_prep_uw(const float* __restrict__ U, const float* __restrict__ wqc) {
    const int q = blockIdx.x, t = threadIdx.x;
    const int i = q * 1024 + t * 4;
    float4 a = *(const float4*)(U + i);
    float4 w = ((const float4*)wqc)[t];
    a.x *= w.x; a.y *= w.y; a.z *= w.z; a.w *= w.w;
    uint32_t h0, h1, l0, l1;
    split4(a.x, a.y, a.z, a.w, h0, h1, l0, l1);
    *(uint2*)((uint16_t*)g_B1h + i) = make_uint2(h0, h1);
    *(uint2*)((uint16_t*)g_B1l + i) = make_uint2(l0, l1);
}

// ---------------- prep: transpose+split (U * rz)^T -----------------------------
__global__ void k_prep_ut(const float* __restrict__ U) {
    __shared__ float t[32][33];
    const int tx = threadIdx.x & 31, ty = threadIdx.x >> 5;
    const int d0 = blockIdx.x * 32, q0 = blockIdx.y * 32;
#pragma unroll
    for (int i = 0; i < 4; ++i)
        t[ty + 8 * i][tx] = U[(size_t)(q0 + ty + 8 * i) * 1024 + d0 + tx];
    __syncthreads();
#pragma unroll
    for (int i = 0; i < 4; ++i) {
        const int d = d0 + ty + 8 * i;
        const int q = q0 + tx;
        const float v = t[tx][ty + 8 * i] * g_rz[q];
        const uint32_t b = __float_as_uint(v);
        ((uint16_t*)g_B2h)[(size_t)d * 1024 + q] = (uint16_t)(b >> 16);
        const float l = v - __uint_as_float(b & 0xffff0000u);
        ((__nv_bfloat16*)g_B2l)[(size_t)d * 1024 + q] = __float2bfloat16(l);
    }
}

// -------- GEMM: 3-stage cp.async, K=32/stage, 8 warps 64x32, 2 CTA/SM ---------
// stage = Ah(8K) | Al(8K) | Bh(8K) | Bl(8K) = 32KB, 3 stages = 96KB
// rows are 64B (32 bf16); chunk swizzle: ch ^= (row>>1)&3
#define TS    32768u
#define O_AL  8192u
#define O_BH  16384u
#define O_BL  24576u
#define NSTG  3

__device__ __forceinline__ void fill_stage(uint32_t sbuf,
                                           const __nv_bfloat16* Ah, const __nv_bfloat16* Al,
                                           const __nv_bfloat16* Bh, const __nv_bfloat16* Bl,
                                           int m0, int n0, int k0, int t) {
#pragma unroll
    for (int u = 0; u < 2; ++u) {
        const int row = (t >> 2) + u * 64, ch = t & 3;
        const int chs = ch ^ ((row >> 1) & 3);
        const uint32_t d = sbuf + (uint32_t)(row * 64 + chs * 16);
        const size_t oa = (size_t)(m0 + row) * 1024 + k0 + ch * 8;
        const size_t ob = (size_t)(n0 + row) * 1024 + k0 + ch * 8;
        CP_ASYNC(d,        Ah + oa);
        CP_ASYNC(d + O_AL, Al + oa);
        CP_ASYNC(d + O_BH, Bh + ob);
        CP_ASYNC(d + O_BL, Bl + ob);
    }
}

template <int PASS>
__global__ __launch_bounds__(256, 2)
void k_mma(const __nv_bfloat16* __restrict__ Ah, const __nv_bfloat16* __restrict__ Al,
           const __nv_bfloat16* __restrict__ Bh, const __nv_bfloat16* __restrict__ Bl,
           const float* __restrict__ bqc, float* __restrict__ out) {
    extern __shared__ char sm[];
    const uint32_t sb = smem_u32(sm);
    const int tid = threadIdx.x;
    const int lane = tid & 31, wid = tid >> 5;
    const int wm = wid & 1, wn = wid >> 1;           // 2 x 4 warps, warp tile 64x32
    const int g = lane >> 2, tq = lane & 3;
    const int m0 = blockIdx.y * 128, n0 = blockIdx.x * 128;
    const int lr = lane & 15, lc = lane >> 4;

    float4 acc[4][4];
#pragma unroll
    for (int i = 0; i < 4; ++i)
#pragma unroll
        for (int j = 0; j < 4; ++j) acc[i][j] = make_float4(0.f, 0.f, 0.f, 0.f);

    fill_stage(sb, Ah, Al, Bh, Bl, m0, n0, 0, tid);       CP_COMMIT();
    fill_stage(sb + TS, Ah, Al, Bh, Bl, m0, n0, 32, tid); CP_COMMIT();

    for (int s = 0; s < 32; ++s) {
        CP_WAIT1();
        __syncthreads();
        const uint32_t buf = sb + (uint32_t)(s % 3) * TS;

#pragma unroll
        for (int kk = 0; kk < 2; ++kk) {
            uint32_t ah[4][4], al[4][4], bh[2][4], bl[2][4];
#pragma unroll
            for (int mt = 0; mt < 4; ++mt) {
                const int row = wm * 64 + mt * 16 + lr;
                const int ch = kk * 2 + lc;
                const uint32_t off = (uint32_t)(row * 64 + ((ch ^ ((row >> 1) & 3)) * 16));
                ldsm4(ah[mt], buf + off);
                ldsm4(al[mt], buf + O_AL + off);
            }
#pragma unroll
            for (int nb = 0; nb < 2; ++nb) {
                const int row = wn * 32 + nb * 16 + lr;
                const int ch = kk * 2 + lc;
                const uint32_t off = (uint32_t)(row * 64 + ((ch ^ ((row >> 1) & 3)) * 16));
                ldsm4(bh[nb], buf + O_BH + off);
                ldsm4(bl[nb], buf + O_BL + off);
            }
#pragma unroll
            for (int mt = 0; mt < 4; ++mt)
#pragma unroll
                for (int nt = 0; nt < 4; ++nt) {
                    const int nb = nt >> 1, p = nt & 1;
                    mma16816(acc[mt][nt], ah[mt], bh[nb][p], bh[nb][p + 2]);
                    mma16816(acc[mt][nt], ah[mt], bl[nb][p], bl[nb][p + 2]);
                    mma16816(acc[mt][nt], al[mt], bh[nb][p], bh[nb][p + 2]);
                }
        }

        if (s < 30)
            fill_stage(sb + (uint32_t)((s + 2) % 3) * TS, Ah, Al, Bh, Bl,
                       m0, n0, (s + 2) * 32, tid);
        CP_COMMIT();
    }
    __syncthreads();

    if (PASS == 1) {
        const float bq = bqc[0];
        float* s_cp = (float*)sm;  // [2][128] overlay
        float cs[4][2];
#pragma unroll
        for (int nt = 0; nt < 4; ++nt) { cs[nt][0] = 0.f; cs[nt][1] = 0.f; }
#pragma unroll
        for (int mt = 0; mt < 4; ++mt) {
            const int row = m0 + wm * 64 + mt * 16 + g;
            const float ct0 = g_cterm[row], ct1 = g_cterm[row + 8];
#pragma unroll
            for (int nt = 0; nt < 4; ++nt) {
                const int col = n0 + wn * 32 + nt * 8 + tq * 2;
                const float q0 = g_qterm[col] + bq, q1 = g_qterm[col + 1] + bq;
                const float4 c = acc[mt][nt];
                const float e00 = __expf(c.x + ct0 + q0), e01 = __expf(c.y + ct0 + q1);
                const float e10 = __expf(c.z + ct1 + q0), e11 = __expf(c.w + ct1 + q1);
                uint32_t h0, h1, l0, l1;
                split4(e00, e01, e10, e11, h0, h1, l0, l1);
                const size_t o0 = (size_t)row * 1024 + col;
                const size_t o1 = (size_t)(row + 8) * 1024 + col;
                *(uint32_t*)((uint16_t*)g_eh + o0) = h0;
                *(uint32_t*)((uint16_t*)g_el + o0) = l0;
                *(uint32_t*)((uint16_t*)g_eh + o1) = h1;
                *(uint32_t*)((uint16_t*)g_el + o1) = l1;
                cs[nt][0] += e00 + e10;
                cs[nt][1] += e01 + e11;
            }
        }
#pragma unroll
        for (int nt = 0; nt < 4; ++nt)
#pragma unroll
            for (int o = 4; o < 32; o <<= 1) {
                cs[nt][0] += __shfl_xor_sync(0xffffffffu, cs[nt][0], o);
                cs[nt][1] += __shfl_xor_sync(0xffffffffu, cs[nt][1], o);
            }
        if (g == 0) {
#pragma unroll
            for (int nt = 0; nt < 4; ++nt) {
                const int col = wn * 32 + nt * 8 + tq * 2;
                s_cp[wm * 128 + col] = cs[nt][0];
                s_cp[wm * 128 + col + 1] = cs[nt][1];
            }
        }
        __syncthreads();
        if (tid < 128) {
            const float v = s_cp[tid] + s_cp[128 + tid];
            g_colpart[blockIdx.y * 1024 + n0 + tid] = v;
        }
    } else {
#pragma unroll
        for (int mt = 0; mt < 4; ++mt) {
            const int row = m0 + wm * 64 + mt * 16 + g;
#pragma unroll
            for (int nt = 0; nt < 4; ++nt) {
                const int col = n0 + wn * 32 + nt * 8 + tq * 2;
                const float4 c = acc[mt][nt];
                *(float2*)(out + (size_t)row * 1024 + col) = make_float2(c.x, c.y);
                *(float2*)(out + (size_t)(row + 8) * 1024 + col) = make_float2(c.z, c.w);
            }
        }
    }
}

// ---------------- Z_q reduction (16 blocks, was 4) ------------------------------
__global__ void k_colfin() {
    const int q = blockIdx.x * 64 + threadIdx.x;
    float s = 0.f;
#pragma unroll
    for (int i = 0; i < 64; ++i) s += g_colpart[i * 1024 + q];
    g_rz[q] = 1.f / s;
}

// ---------------- c2q softmax ---------------------------------------------------
__global__ void k_c2q() {
    const int t = threadIdx.x;
    const int lane = t & 31, wid = t >> 5;
    __shared__ float sred[32];
    __shared__ float sbc[2];
    float m = -1e30f;
    for (int c = t; c < C_LEN; c += 1024) m = fmaxf(m, g_bmax[c]);
#pragma unroll
    for (int o = 16; o; o >>= 1) m = fmaxf(m, __shfl_xor_sync(0xffffffffu, m, o));
    if (lane == 0) sred[wid] = m;
    __syncthreads();
    if (t < 32) {
        float v = sred[t];
#pragma unroll
        for (int o = 16; o; o >>= 1) v = fmaxf(v, __shfl_xor_sync(0xffffffffu, v, o));
        if (t == 0) sbc[0] = v;
    }
    __syncthreads();
    const float mm = sbc[0];
    float z = 0.f;
    for (int c = t; c < C_LEN; c += 1024) z += expf(g_bmax[c] - mm);
#pragma unroll
    for (int o = 16; o; o >>= 1) z += __shfl_xor_sync(0xffffffffu, z, o);
    __syncthreads();
    if (lane == 0) sred[wid] = z;
    __syncthreads();
    if (t < 32) {
        float v = sred[t];
#pragma unroll
        for (int o = 16; o; o >>= 1) v += __shfl_xor_sync(0xffffffffu, v, o);
        if (t == 0) sbc[1] = v;
    }
    __syncthreads();
    const float rz = 1.f / sbc[1];
    for (int c = t; c < C_LEN; c += 1024) g_w[c] = expf(g_bmax[c] - mm) * rz;
}

// ---------------- weighted column sum of H ---------------------------------------
__global__ void k_hpart(const float* __restrict__ H) {
    const int chunk = blockIdx.x, t = threadIdx.x;
    float a0 = 0.f, a1 = 0.f, a2 = 0.f, a3 = 0.f;
    const int c0 = chunk * 128;
    for (int c = c0; c < c0 + 128; ++c) {
        const float wv = g_w[c];
        const float* hr = H + (size_t)c * 1024;
        a0 = fmaf(wv, hr[t], a0);
        a1 = fmaf(wv, hr[t + 256], a1);
        a2 = fmaf(wv, hr[t + 512], a2);
        a3 = fmaf(wv, hr[t + 768], a3);
    }
    g_hpart[chunk][t] = a0;
    g_hpart[chunk][t + 256] = a1;
    g_hpart[chunk][t + 512] = a2;
    g_hpart[chunk][t + 768] = a3;
}

__global__ void k_hred() {
    const int d = blockIdx.x * 64 + threadIdx.x;
    float s = 0.f;
#pragma unroll
    for (int i = 0; i < 64; ++i) s += g_hpart[i][d];
    g_hrow[d] = s;
}

__global__ void k_bcast(float* __restrict__ out) {
    const float4 v = ((const float4*)g_hrow)[threadIdx.x];
    ((float4*)(out + (size_t)C_LEN * D_DIM))[blockIdx.x * 256 + threadIdx.x] = v;
}

// ---------------- launch ----------------------------------------------------------
extern "C" void kernel_launch(void* const* d_in, const int* in_sizes, int n_in,
                              void* d_out, int out_size) {
    const float* H   = (const float*)d_in[0];
    const float* U   = (const float*)d_in[1];
    const float* wq  = (const float*)d_in[2];
    const float* bq  = (const float*)d_in[3];
    const float* wc  = (const float*)d_in[4];
    const float* bc  = (const float*)d_in[5];
    const float* wqc = (const float*)d_in[6];
    const float* bqc = (const float*)d_in[7];
    float* out = (float*)d_out;

    static bool s_attr = false;
    if (!s_attr) {
        cudaFuncSetAttribute(k_mma<1>, cudaFuncAttributeMaxDynamicSharedMemorySize, NSTG * TS);
        cudaFuncSetAttribute(k_mma<2>, cudaFuncAttributeMaxDynamicSharedMemorySize, NSTG * TS);
        s_attr = true;
    }

    void *hh, *hl, *b1h, *b1l, *eh, *el, *b2h, *b2l;
    cudaGetSymbolAddress(&hh, g_Hh);
    cudaGetSymbolAddress(&hl, g_Hl);
    cudaGetSymbolAddress(&b1h, g_B1h);
    cudaGetSymbolAddress(&b1l, g_B1l);
    cudaGetSymbolAddress(&eh, g_eh);
    cudaGetSymbolAddress(&el, g_el);
    cudaGetSymbolAddress(&b2h, g_B2h);
    cudaGetSymbolAddress(&b2l, g_B2l);

    k_stats<<<C_LEN + Q_LEN, 256>>>(H, U, wq, bq, wc, bc);
    k_prep_h<<<C_LEN * D_DIM / 1024, 256>>>(H);
    k_prep_uw<<<Q_LEN, 256>>>(U, wqc);
    k_mma<1><<<dim3(8, 64), 256, NSTG * TS>>>((const __nv_bfloat16*)hh, (const __nv_bfloat16*)hl,
                                              (const __nv_bfloat16*)b1h, (const __nv_bfloat16*)b1l,
                                              bqc, nullptr);
    k_colfin<<<16, 64>>>();
    k_prep_ut<<<dim3(32, 32), 256>>>(U);
    k_mma<2><<<dim3(8, 64), 256, NSTG * TS>>>((const __nv_bfloat16*)eh, (const __nv_bfloat16*)el,
                                              (const __nv_bfloat16*)b2h, (const __nv_bfloat16*)b2l,
                                              bqc, out);
    k_c2q<<<1, 1024>>>();
    k_hpart<<<64, 256>>>(H);
    k_hred<<<16, 64>>>();
    k_bcast<<<C_LEN, 256>>>(out);
}

// round 10
// speedup vs baseline: 1.1251x; 1.0209x over previous
#include <cuda_runtime.h>
#include <cuda_bf16.h>
#include <cstdint>
#include <math.h>

#define C_LEN 8192
#define Q_LEN 1024
#define D_DIM 1024

// ---------------- scratch (device globals) -----------------------------------
__device__ __align__(16) __nv_bfloat16 g_Hh[C_LEN * D_DIM];
__device__ __align__(16) __nv_bfloat16 g_Hl[C_LEN * D_DIM];
__device__ __align__(16) __nv_bfloat16 g_B1h[Q_LEN * D_DIM];
__device__ __align__(16) __nv_bfloat16 g_B1l[Q_LEN * D_DIM];
__device__ __align__(16) __nv_bfloat16 g_B2h[D_DIM * Q_LEN];
__device__ __align__(16) __nv_bfloat16 g_B2l[D_DIM * Q_LEN];
__device__ __align__(16) __nv_bfloat16 g_eh[C_LEN * Q_LEN];
__device__ __align__(16) __nv_bfloat16 g_el[C_LEN * Q_LEN];
__device__ __align__(16) float g_qterm[Q_LEN];
__device__ __align__(16) float g_cterm[C_LEN];
__device__ __align__(16) float g_bmax[C_LEN];
__device__ __align__(16) float g_colpart[64 * Q_LEN];
__device__ __align__(16) float g_rz[Q_LEN];
__device__ __align__(16) float g_w[C_LEN];
__device__ __align__(16) float g_hpart[64][D_DIM];
__device__ __align__(16) float g_hrow[D_DIM];

// ---------------- helpers -----------------------------------------------------
__device__ __forceinline__ uint32_t smem_u32(const void* p) {
    uint32_t a;
    asm("{ .reg .u64 t; cvta.to.shared.u64 t, %1; cvt.u32.u64 %0, t; }" : "=r"(a) : "l"(p));
    return a;
}
__device__ __forceinline__ uint32_t pack_lo_bf16x2(float l0, float l1) {
    uint32_t r;
    asm("cvt.rn.bf16x2.f32 %0, %1, %2;" : "=r"(r) : "f"(l1), "f"(l0));
    return r;
}
__device__ __forceinline__ void split4(float x, float y, float z, float w,
                                       uint32_t& h0, uint32_t& h1,
                                       uint32_t& l0, uint32_t& l1) {
    uint32_t bx = __float_as_uint(x), by = __float_as_uint(y);
    uint32_t bz = __float_as_uint(z), bw = __float_as_uint(w);
    h0 = __byte_perm(bx, by, 0x7632);
    h1 = __byte_perm(bz, bw, 0x7632);
    l0 = pack_lo_bf16x2(x - __uint_as_float(bx & 0xffff0000u),
                        y - __uint_as_float(by & 0xffff0000u));
    l1 = pack_lo_bf16x2(z - __uint_as_float(bz & 0xffff0000u),
                        w - __uint_as_float(bw & 0xffff0000u));
}
__device__ __forceinline__ void mma16816(float4& c, const uint32_t a[4],
                                         uint32_t b0, uint32_t b1) {
    asm volatile(
        "mma.sync.aligned.m16n8k16.row.col.f32.bf16.bf16.f32 "
        "{%0,%1,%2,%3}, {%4,%5,%6,%7}, {%8,%9}, {%0,%1,%2,%3};"
        : "+f"(c.x), "+f"(c.y), "+f"(c.z), "+f"(c.w)
        : "r"(a[0]), "r"(a[1]), "r"(a[2]), "r"(a[3]), "r"(b0), "r"(b1));
}
__device__ __forceinline__ void ldsm4(uint32_t d[4], uint32_t a) {
    asm volatile("ldmatrix.sync.aligned.m8n8.x4.shared.b16 {%0,%1,%2,%3}, [%4];"
                 : "=r"(d[0]), "=r"(d[1]), "=r"(d[2]), "=r"(d[3]) : "r"(a));
}
#define CP_ASYNC(d, s) asm volatile("cp.async.ca.shared.global [%0], [%1], 16;" :: "r"(d), "l"(s) : "memory")
#define CP_COMMIT()    asm volatile("cp.async.commit_group;" ::: "memory")
#define CP_WAIT1()     asm volatile("cp.async.wait_group 1;" ::: "memory")

// ------ fused stats+split: blocks 0..8191 -> H row (stats + Hh/Hl split),
//        blocks 8192..9215 -> U row (qterm + (U*wqc) split) ---------------------
__global__ void k_stats(const float* __restrict__ H, const float* __restrict__ U,
                        const float* __restrict__ wq, const float* __restrict__ bq,
                        const float* __restrict__ wc, const float* __restrict__ bc,
                        const float* __restrict__ wqc) {
    const int t = threadIdx.x;
    __shared__ float sp[8], sm2[8];
    if (blockIdx.x < C_LEN) {
        const int c = blockIdx.x;
        const int i = c * 1024 + t * 4;
        float4 h = *(const float4*)(H + i);
        float4 w = ((const float4*)wc)[t];
        // split H -> bf16 hi/lo
        uint32_t h0, h1, l0, l1;
        split4(h.x, h.y, h.z, h.w, h0, h1, l0, l1);
        *(uint2*)((uint16_t*)g_Hh + i) = make_uint2(h0, h1);
        *(uint2*)((uint16_t*)g_Hl + i) = make_uint2(l0, l1);
        float p = h.x * w.x + h.y * w.y + h.z * w.z + h.w * w.w;
        float m = fmaxf(fmaxf(h.x, h.y), fmaxf(h.z, h.w));
#pragma unroll
        for (int o = 16; o; o >>= 1) {
            p += __shfl_down_sync(0xffffffffu, p, o);
            m = fmaxf(m, __shfl_down_sync(0xffffffffu, m, o));
        }
        if ((t & 31) == 0) { sp[t >> 5] = p; sm2[t >> 5] = m; }
        __syncthreads();
        if (t == 0) {
            float pp = sp[0], mm = sm2[0];
#pragma unroll
            for (int i2 = 1; i2 < 8; ++i2) { pp += sp[i2]; mm = fmaxf(mm, sm2[i2]); }
            g_cterm[c] = pp + bc[0];
            g_bmax[c] = mm;
        }
    } else {
        const int n = blockIdx.x - C_LEN;
        const int i = n * 1024 + t * 4;
        float4 u = *(const float4*)(U + i);
        float4 w = ((const float4*)wq)[t];
        float p = u.x * w.x + u.y * w.y + u.z * w.z + u.w * w.w;
        // split (U * wqc)
        float4 wq2 = ((const float4*)wqc)[t];
        float4 a = make_float4(u.x * wq2.x, u.y * wq2.y, u.z * wq2.z, u.w * wq2.w);
        uint32_t h0, h1, l0, l1;
        split4(a.x, a.y, a.z, a.w, h0, h1, l0, l1);
        *(uint2*)((uint16_t*)g_B1h + i) = make_uint2(h0, h1);
        *(uint2*)((uint16_t*)g_B1l + i) = make_uint2(l0, l1);
#pragma unroll
        for (int o = 16; o; o >>= 1) p += __shfl_down_sync(0xffffffffu, p, o);
        if ((t & 31) == 0) sp[t >> 5] = p;
        __syncthreads();
        if (t == 0) {
            float s = sp[0];
#pragma unroll
            for (int i2 = 1; i2 < 8; ++i2) s += sp[i2];
            g_qterm[n] = s + bq[0];
        }
    }
}

// ---------------- prep: transpose+split (U * rz)^T -----------------------------
__global__ void k_prep_ut(const float* __restrict__ U) {
    __shared__ float t[32][33];
    const int tx = threadIdx.x & 31, ty = threadIdx.x >> 5;
    const int d0 = blockIdx.x * 32, q0 = blockIdx.y * 32;
#pragma unroll
    for (int i = 0; i < 4; ++i)
        t[ty + 8 * i][tx] = U[(size_t)(q0 + ty + 8 * i) * 1024 + d0 + tx];
    __syncthreads();
#pragma unroll
    for (int i = 0; i < 4; ++i) {
        const int d = d0 + ty + 8 * i;
        const int q = q0 + tx;
        const float v = t[tx][ty + 8 * i] * g_rz[q];
        const uint32_t b = __float_as_uint(v);
        ((uint16_t*)g_B2h)[(size_t)d * 1024 + q] = (uint16_t)(b >> 16);
        const float l = v - __uint_as_float(b & 0xffff0000u);
        ((__nv_bfloat16*)g_B2l)[(size_t)d * 1024 + q] = __float2bfloat16(l);
    }
}

// -------- GEMM: 3-stage cp.async, K=32/stage, 8 warps 64x32, 2 CTA/SM ---------
#define TS    32768u
#define O_AL  8192u
#define O_BH  16384u
#define O_BL  24576u
#define NSTG  3

__device__ __forceinline__ void fill_stage(uint32_t sbuf,
                                           const __nv_bfloat16* Ah, const __nv_bfloat16* Al,
                                           const __nv_bfloat16* Bh, const __nv_bfloat16* Bl,
                                           int m0, int n0, int k0, int t) {
#pragma unroll
    for (int u = 0; u < 2; ++u) {
        const int row = (t >> 2) + u * 64, ch = t & 3;
        const int chs = ch ^ ((row >> 1) & 3);
        const uint32_t d = sbuf + (uint32_t)(row * 64 + chs * 16);
        const size_t oa = (size_t)(m0 + row) * 1024 + k0 + ch * 8;
        const size_t ob = (size_t)(n0 + row) * 1024 + k0 + ch * 8;
        CP_ASYNC(d,        Ah + oa);
        CP_ASYNC(d + O_AL, Al + oa);
        CP_ASYNC(d + O_BH, Bh + ob);
        CP_ASYNC(d + O_BL, Bl + ob);
    }
}

template <int PASS>
__global__ __launch_bounds__(256, 2)
void k_mma(const __nv_bfloat16* __restrict__ Ah, const __nv_bfloat16* __restrict__ Al,
           const __nv_bfloat16* __restrict__ Bh, const __nv_bfloat16* __restrict__ Bl,
           const float* __restrict__ bqc, float* __restrict__ out) {
    extern __shared__ char sm[];
    const uint32_t sb = smem_u32(sm);
    const int tid = threadIdx.x;
    const int lane = tid & 31, wid = tid >> 5;
    const int wm = wid & 1, wn = wid >> 1;           // 2 x 4 warps, warp tile 64x32
    const int g = lane >> 2, tq = lane & 3;
    const int m0 = blockIdx.y * 128, n0 = blockIdx.x * 128;
    const int lr = lane & 15, lc = lane >> 4;

    float4 acc[4][4];
#pragma unroll
    for (int i = 0; i < 4; ++i)
#pragma unroll
        for (int j = 0; j < 4; ++j) acc[i][j] = make_float4(0.f, 0.f, 0.f, 0.f);

    fill_stage(sb, Ah, Al, Bh, Bl, m0, n0, 0, tid);       CP_COMMIT();
    fill_stage(sb + TS, Ah, Al, Bh, Bl, m0, n0, 32, tid); CP_COMMIT();

    for (int s = 0; s < 32; ++s) {
        CP_WAIT1();
        __syncthreads();
        const uint32_t buf = sb + (uint32_t)(s % 3) * TS;

#pragma unroll
        for (int kk = 0; kk < 2; ++kk) {
            uint32_t ah[4][4], al[4][4], bh[2][4], bl[2][4];
#pragma unroll
            for (int mt = 0; mt < 4; ++mt) {
                const int row = wm * 64 + mt * 16 + lr;
                const int ch = kk * 2 + lc;
                const uint32_t off = (uint32_t)(row * 64 + ((ch ^ ((row >> 1) & 3)) * 16));
                ldsm4(ah[mt], buf + off);
                ldsm4(al[mt], buf + O_AL + off);
            }
#pragma unroll
            for (int nb = 0; nb < 2; ++nb) {
                const int row = wn * 32 + nb * 16 + lr;
                const int ch = kk * 2 + lc;
                const uint32_t off = (uint32_t)(row * 64 + ((ch ^ ((row >> 1) & 3)) * 16));
                ldsm4(bh[nb], buf + O_BH + off);
                ldsm4(bl[nb], buf + O_BL + off);
            }
            // product-major ordering: RAW reuse distance on each accumulator = 16 MMAs
#pragma unroll
            for (int mt = 0; mt < 4; ++mt)
#pragma unroll
                for (int nt = 0; nt < 4; ++nt) {
                    const int nb = nt >> 1, p = nt & 1;
                    mma16816(acc[mt][nt], ah[mt], bh[nb][p], bh[nb][p + 2]);
                }
#pragma unroll
            for (int mt = 0; mt < 4; ++mt)
#pragma unroll
                for (int nt = 0; nt < 4; ++nt) {
                    const int nb = nt >> 1, p = nt & 1;
                    mma16816(acc[mt][nt], ah[mt], bl[nb][p], bl[nb][p + 2]);
                }
#pragma unroll
            for (int mt = 0; mt < 4; ++mt)
#pragma unroll
                for (int nt = 0; nt < 4; ++nt) {
                    const int nb = nt >> 1, p = nt & 1;
                    mma16816(acc[mt][nt], al[mt], bh[nb][p], bh[nb][p + 2]);
                }
        }

        if (s < 30)
            fill_stage(sb + (uint32_t)((s + 2) % 3) * TS, Ah, Al, Bh, Bl,
                       m0, n0, (s + 2) * 32, tid);
        CP_COMMIT();
    }
    __syncthreads();

    if (PASS == 1) {
        const float bq = bqc[0];
        float* s_cp = (float*)sm;  // [2][128] overlay
        float cs[4][2];
#pragma unroll
        for (int nt = 0; nt < 4; ++nt) { cs[nt][0] = 0.f; cs[nt][1] = 0.f; }
#pragma unroll
        for (int mt = 0; mt < 4; ++mt) {
            const int row = m0 + wm * 64 + mt * 16 + g;
            const float ct0 = g_cterm[row], ct1 = g_cterm[row + 8];
#pragma unroll
            for (int nt = 0; nt < 4; ++nt) {
                const int col = n0 + wn * 32 + nt * 8 + tq * 2;
                const float q0 = g_qterm[col] + bq, q1 = g_qterm[col + 1] + bq;
                const float4 c = acc[mt][nt];
                const float e00 = __expf(c.x + ct0 + q0), e01 = __expf(c.y + ct0 + q1);
                const float e10 = __expf(c.z + ct1 + q0), e11 = __expf(c.w + ct1 + q1);
                uint32_t h0, h1, l0, l1;
                split4(e00, e01, e10, e11, h0, h1, l0, l1);
                const size_t o0 = (size_t)row * 1024 + col;
                const size_t o1 = (size_t)(row + 8) * 1024 + col;
                *(uint32_t*)((uint16_t*)g_eh + o0) = h0;
                *(uint32_t*)((uint16_t*)g_el + o0) = l0;
                *(uint32_t*)((uint16_t*)g_eh + o1) = h1;
                *(uint32_t*)((uint16_t*)g_el + o1) = l1;
                cs[nt][0] += e00 + e10;
                cs[nt][1] += e01 + e11;
            }
        }
#pragma unroll
        for (int nt = 0; nt < 4; ++nt)
#pragma unroll
            for (int o = 4; o < 32; o <<= 1) {
                cs[nt][0] += __shfl_xor_sync(0xffffffffu, cs[nt][0], o);
                cs[nt][1] += __shfl_xor_sync(0xffffffffu, cs[nt][1], o);
            }
        if (g == 0) {
#pragma unroll
            for (int nt = 0; nt < 4; ++nt) {
                const int col = wn * 32 + nt * 8 + tq * 2;
                s_cp[wm * 128 + col] = cs[nt][0];
                s_cp[wm * 128 + col + 1] = cs[nt][1];
            }
        }
        __syncthreads();
        if (tid < 128) {
            const float v = s_cp[tid] + s_cp[128 + tid];
            g_colpart[blockIdx.y * 1024 + n0 + tid] = v;
        }
    } else {
#pragma unroll
        for (int mt = 0; mt < 4; ++mt) {
            const int row = m0 + wm * 64 + mt * 16 + g;
#pragma unroll
            for (int nt = 0; nt < 4; ++nt) {
                const int col = n0 + wn * 32 + nt * 8 + tq * 2;
                const float4 c = acc[mt][nt];
                *(float2*)(out + (size_t)row * 1024 + col) = make_float2(c.x, c.y);
                *(float2*)(out + (size_t)(row + 8) * 1024 + col) = make_float2(c.z, c.w);
            }
        }
    }
}

// ---------------- Z_q reduction --------------------------------------------------
__global__ void k_colfin() {
    const int q = blockIdx.x * 64 + threadIdx.x;
    float s = 0.f;
#pragma unroll
    for (int i = 0; i < 64; ++i) s += g_colpart[i * 1024 + q];
    g_rz[q] = 1.f / s;
}

// ---------------- c2q softmax ---------------------------------------------------
__global__ void k_c2q() {
    const int t = threadIdx.x;
    const int lane = t & 31, wid = t >> 5;
    __shared__ float sred[32];
    __shared__ float sbc[2];
    float m = -1e30f;
    for (int c = t; c < C_LEN; c += 1024) m = fmaxf(m, g_bmax[c]);
#pragma unroll
    for (int o = 16; o; o >>= 1) m = fmaxf(m, __shfl_xor_sync(0xffffffffu, m, o));
    if (lane == 0) sred[wid] = m;
    __syncthreads();
    if (t < 32) {
        float v = sred[t];
#pragma unroll
        for (int o = 16; o; o >>= 1) v = fmaxf(v, __shfl_xor_sync(0xffffffffu, v, o));
        if (t == 0) sbc[0] = v;
    }
    __syncthreads();
    const float mm = sbc[0];
    float z = 0.f;
    for (int c = t; c < C_LEN; c += 1024) z += expf(g_bmax[c] - mm);
#pragma unroll
    for (int o = 16; o; o >>= 1) z += __shfl_xor_sync(0xffffffffu, z, o);
    __syncthreads();
    if (lane == 0) sred[wid] = z;
    __syncthreads();
    if (t < 32) {
        float v = sred[t];
#pragma unroll
        for (int o = 16; o; o >>= 1) v += __shfl_xor_sync(0xffffffffu, v, o);
        if (t == 0) sbc[1] = v;
    }
    __syncthreads();
    const float rz = 1.f / sbc[1];
    for (int c = t; c < C_LEN; c += 1024) g_w[c] = expf(g_bmax[c] - mm) * rz;
}

// ---------------- weighted column sum of H ---------------------------------------
__global__ void k_hpart(const float* __restrict__ H) {
    const int chunk = blockIdx.x, t = threadIdx.x;
    float a0 = 0.f, a1 = 0.f, a2 = 0.f, a3 = 0.f;
    const int c0 = chunk * 128;
    for (int c = c0; c < c0 + 128; ++c) {
        const float wv = g_w[c];
        const float* hr = H + (size_t)c * 1024;
        a0 = fmaf(wv, hr[t], a0);
        a1 = fmaf(wv, hr[t + 256], a1);
        a2 = fmaf(wv, hr[t + 512], a2);
        a3 = fmaf(wv, hr[t + 768], a3);
    }
    g_hpart[chunk][t] = a0;
    g_hpart[chunk][t + 256] = a1;
    g_hpart[chunk][t + 512] = a2;
    g_hpart[chunk][t + 768] = a3;
}

__global__ void k_hred() {
    const int d = blockIdx.x * 64 + threadIdx.x;
    float s = 0.f;
#pragma unroll
    for (int i = 0; i < 64; ++i) s += g_hpart[i][d];
    g_hrow[d] = s;
}

__global__ void k_bcast(float* __restrict__ out) {
    const float4 v = ((const float4*)g_hrow)[threadIdx.x];
    ((float4*)(out + (size_t)C_LEN * D_DIM))[blockIdx.x * 256 + threadIdx.x] = v;
}

// ---------------- launch ----------------------------------------------------------
extern "C" void kernel_launch(void* const* d_in, const int* in_sizes, int n_in,
                              void* d_out, int out_size) {
    const float* H   = (const float*)d_in[0];
    const float* U   = (const float*)d_in[1];
    const float* wq  = (const float*)d_in[2];
    const float* bq  = (const float*)d_in[3];
    const float* wc  = (const float*)d_in[4];
    const float* bc  = (const float*)d_in[5];
    const float* wqc = (const float*)d_in[6];
    const float* bqc = (const float*)d_in[7];
    float* out = (float*)d_out;

    static bool s_attr = false;
    if (!s_attr) {
        cudaFuncSetAttribute(k_mma<1>, cudaFuncAttributeMaxDynamicSharedMemorySize, NSTG * TS);
        cudaFuncSetAttribute(k_mma<2>, cudaFuncAttributeMaxDynamicSharedMemorySize, NSTG * TS);
        s_attr = true;
    }

    void *hh, *hl, *b1h, *b1l, *eh, *el, *b2h, *b2l;
    cudaGetSymbolAddress(&hh, g_Hh);
    cudaGetSymbolAddress(&hl, g_Hl);
    cudaGetSymbolAddress(&b1h, g_B1h);
    cudaGetSymbolAddress(&b1l, g_B1l);
    cudaGetSymbolAddress(&eh, g_eh);
    cudaGetSymbolAddress(&el, g_el);
    cudaGetSymbolAddress(&b2h, g_B2h);
    cudaGetSymbolAddress(&b2l, g_B2l);

    k_stats<<<C_LEN + Q_LEN, 256>>>(H, U, wq, bq, wc, bc, wqc);
    k_mma<1><<<dim3(8, 64), 256, NSTG * TS>>>((const __nv_bfloat16*)hh, (const __nv_bfloat16*)hl,
                                              (const __nv_bfloat16*)b1h, (const __nv_bfloat16*)b1l,
                                              bqc, nullptr);
    k_colfin<<<16, 64>>>();
    k_prep_ut<<<dim3(32, 32), 256>>>(U);
    k_mma<2><<<dim3(8, 64), 256, NSTG * TS>>>((const __nv_bfloat16*)eh, (const __nv_bfloat16*)el,
                                              (const __nv_bfloat16*)b2h, (const __nv_bfloat16*)b2l,
                                              bqc, out);
    k_c2q<<<1, 1024>>>();
    k_hpart<<<64, 256>>>(H);
    k_hred<<<16, 64>>>();
    k_bcast<<<C_LEN, 256>>>(out);
}

// round 11
// speedup vs baseline: 1.8683x; 1.6606x over previous
#include <cuda_runtime.h>
#include <cuda_fp16.h>
#include <cstdint>
#include <math.h>

#define C_LEN 8192
#define Q_LEN 1024
#define D_DIM 1024

// ---------------- scratch (device globals) -----------------------------------
__device__ __align__(16) __half g_Hh[C_LEN * D_DIM];     // H hi (fp16 RN)
__device__ __align__(16) __half g_Hl[C_LEN * D_DIM];     // H residual (fp16)
__device__ __align__(16) __half g_B1[Q_LEN * D_DIM];     // 32 * U * wqc (fp16 RN)
__device__ __align__(16) __half g_B2[D_DIM * Q_LEN];     // 16 * rz * U^T (fp16 RN)
__device__ __align__(16) __half g_e[C_LEN * Q_LEN];      // exp(s)/16 (fp16 RN)
__device__ __align__(16) float g_qterm[Q_LEN];
__device__ __align__(16) float g_cterm[C_LEN];
__device__ __align__(16) float g_bmax[C_LEN];
__device__ __align__(16) float g_colpart[64 * Q_LEN];
__device__ __align__(16) float g_rz[Q_LEN];
__device__ __align__(16) float g_w[C_LEN];
__device__ __align__(16) float g_hpart[64][D_DIM];
__device__ __align__(16) float g_hrow[D_DIM];

// ---------------- helpers -----------------------------------------------------
__device__ __forceinline__ uint32_t smem_u32(const void* p) {
    uint32_t a;
    asm("{ .reg .u64 t; cvta.to.shared.u64 t, %1; cvt.u32.u64 %0, t; }" : "=r"(a) : "l"(p));
    return a;
}
__device__ __forceinline__ void mma16816(float4& c, const uint32_t a[4],
                                         uint32_t b0, uint32_t b1) {
    asm volatile(
        "mma.sync.aligned.m16n8k16.row.col.f32.f16.f16.f32 "
        "{%0,%1,%2,%3}, {%4,%5,%6,%7}, {%8,%9}, {%0,%1,%2,%3};"
        : "+f"(c.x), "+f"(c.y), "+f"(c.z), "+f"(c.w)
        : "r"(a[0]), "r"(a[1]), "r"(a[2]), "r"(a[3]), "r"(b0), "r"(b1));
}
__device__ __forceinline__ void ldsm4(uint32_t d[4], uint32_t a) {
    asm volatile("ldmatrix.sync.aligned.m8n8.x4.shared.b16 {%0,%1,%2,%3}, [%4];"
                 : "=r"(d[0]), "=r"(d[1]), "=r"(d[2]), "=r"(d[3]) : "r"(a));
}
#define CP_ASYNC(d, s) asm volatile("cp.async.ca.shared.global [%0], [%1], 16;" :: "r"(d), "l"(s) : "memory")
#define CP_COMMIT()    asm volatile("cp.async.commit_group;" ::: "memory")
#define CP_WAIT1()     asm volatile("cp.async.wait_group 1;" ::: "memory")

__device__ __forceinline__ uint32_t h2_pack(float a, float b) {
    __half2 h = __floats2half2_rn(a, b);
    return *(uint32_t*)&h;
}

// ------ fused stats+split: blocks 0..8191 -> H row, 8192..9215 -> U row --------
__global__ void k_stats(const float* __restrict__ H, const float* __restrict__ U,
                        const float* __restrict__ wq, const float* __restrict__ bq,
                        const float* __restrict__ wc, const float* __restrict__ bc,
                        const float* __restrict__ wqc) {
    const int t = threadIdx.x;
    __shared__ float sp[8], sm2[8];
    if (blockIdx.x < C_LEN) {
        const int c = blockIdx.x;
        const int i = c * 1024 + t * 4;
        float4 h = *(const float4*)(H + i);
        float4 w = ((const float4*)wc)[t];
        // split H -> fp16 hi (RN) + fp16 residual
        float hx = __half2float(__float2half_rn(h.x));
        float hy = __half2float(__float2half_rn(h.y));
        float hz = __half2float(__float2half_rn(h.z));
        float hw = __half2float(__float2half_rn(h.w));
        *(uint2*)((uint16_t*)g_Hh + i) = make_uint2(h2_pack(hx, hy), h2_pack(hz, hw));
        *(uint2*)((uint16_t*)g_Hl + i) = make_uint2(h2_pack(h.x - hx, h.y - hy),
                                                    h2_pack(h.z - hz, h.w - hw));
        float p = h.x * w.x + h.y * w.y + h.z * w.z + h.w * w.w;
        float m = fmaxf(fmaxf(h.x, h.y), fmaxf(h.z, h.w));
#pragma unroll
        for (int o = 16; o; o >>= 1) {
            p += __shfl_down_sync(0xffffffffu, p, o);
            m = fmaxf(m, __shfl_down_sync(0xffffffffu, m, o));
        }
        if ((t & 31) == 0) { sp[t >> 5] = p; sm2[t >> 5] = m; }
        __syncthreads();
        if (t == 0) {
            float pp = sp[0], mm = sm2[0];
#pragma unroll
            for (int i2 = 1; i2 < 8; ++i2) { pp += sp[i2]; mm = fmaxf(mm, sm2[i2]); }
            g_cterm[c] = pp + bc[0];
            g_bmax[c] = mm;
        }
    } else {
        const int n = blockIdx.x - C_LEN;
        const int i = n * 1024 + t * 4;
        float4 u = *(const float4*)(U + i);
        float4 w = ((const float4*)wq)[t];
        float p = u.x * w.x + u.y * w.y + u.z * w.z + u.w * w.w;
        // B1 = 32 * U * wqc, single fp16 RN
        float4 wq2 = ((const float4*)wqc)[t];
        *(uint2*)((uint16_t*)g_B1 + i) =
            make_uint2(h2_pack(32.f * u.x * wq2.x, 32.f * u.y * wq2.y),
                       h2_pack(32.f * u.z * wq2.z, 32.f * u.w * wq2.w));
#pragma unroll
        for (int o = 16; o; o >>= 1) p += __shfl_down_sync(0xffffffffu, p, o);
        if ((t & 31) == 0) sp[t >> 5] = p;
        __syncthreads();
        if (t == 0) {
            float s = sp[0];
#pragma unroll
            for (int i2 = 1; i2 < 8; ++i2) s += sp[i2];
            g_qterm[n] = s + bq[0];
        }
    }
}

// ---------------- prep: transpose B2 = 16 * rz * U^T ---------------------------
__global__ void k_prep_ut(const float* __restrict__ U) {
    __shared__ float t[32][33];
    const int tx = threadIdx.x & 31, ty = threadIdx.x >> 5;
    const int d0 = blockIdx.x * 32, q0 = blockIdx.y * 32;
#pragma unroll
    for (int i = 0; i < 4; ++i)
        t[ty + 8 * i][tx] = U[(size_t)(q0 + ty + 8 * i) * 1024 + d0 + tx];
    __syncthreads();
#pragma unroll
    for (int i = 0; i < 4; ++i) {
        const int d = d0 + ty + 8 * i;
        const int q = q0 + tx;
        const float v = t[tx][ty + 8 * i] * g_rz[q] * 16.f;
        ((__half*)g_B2)[(size_t)d * 1024 + q] = __float2half_rn(v);
    }
}

// -------- GEMM1: 3-stage cp.async, K=32/stage, 8 warps 64x32, 2 products ------
// stage = Ah(8K) | Al(8K) | B(8K) = 24KB, 3 stages = 72KB
#define TS1    24576u
#define O1_AL  8192u
#define O1_B   16384u

__device__ __forceinline__ void fill1(uint32_t sbuf,
                                      const __half* Ah, const __half* Al,
                                      const __half* B, int m0, int n0, int k0, int t) {
#pragma unroll
    for (int u = 0; u < 2; ++u) {
        const int row = (t >> 2) + u * 64, ch = t & 3;
        const int chs = ch ^ ((row >> 1) & 3);
        const uint32_t d = sbuf + (uint32_t)(row * 64 + chs * 16);
        const size_t oa = (size_t)(m0 + row) * 1024 + k0 + ch * 8;
        const size_t ob = (size_t)(n0 + row) * 1024 + k0 + ch * 8;
        CP_ASYNC(d,         Ah + oa);
        CP_ASYNC(d + O1_AL, Al + oa);
        CP_ASYNC(d + O1_B,  B + ob);
    }
}

__global__ __launch_bounds__(256, 2)
void k_mma1(const __half* __restrict__ Ah, const __half* __restrict__ Al,
            const __half* __restrict__ B, const float* __restrict__ bqc) {
    extern __shared__ char sm[];
    const uint32_t sb = smem_u32(sm);
    const int tid = threadIdx.x;
    const int lane = tid & 31, wid = tid >> 5;
    const int wm = wid & 1, wn = wid >> 1;
    const int g = lane >> 2, tq = lane & 3;
    const int m0 = blockIdx.y * 128, n0 = blockIdx.x * 128;
    const int lr = lane & 15, lc = lane >> 4;

    float4 acc[4][4];
#pragma unroll
    for (int i = 0; i < 4; ++i)
#pragma unroll
        for (int j = 0; j < 4; ++j) acc[i][j] = make_float4(0.f, 0.f, 0.f, 0.f);

    fill1(sb, Ah, Al, B, m0, n0, 0, tid);        CP_COMMIT();
    fill1(sb + TS1, Ah, Al, B, m0, n0, 32, tid); CP_COMMIT();

    for (int s = 0; s < 32; ++s) {
        CP_WAIT1();
        __syncthreads();
        const uint32_t buf = sb + (uint32_t)(s % 3) * TS1;

#pragma unroll
        for (int kk = 0; kk < 2; ++kk) {
            uint32_t ah[4][4], al[4][4], bf[2][4];
#pragma unroll
            for (int mt = 0; mt < 4; ++mt) {
                const int row = wm * 64 + mt * 16 + lr;
                const int ch = kk * 2 + lc;
                const uint32_t off = (uint32_t)(row * 64 + ((ch ^ ((row >> 1) & 3)) * 16));
                ldsm4(ah[mt], buf + off);
                ldsm4(al[mt], buf + O1_AL + off);
            }
#pragma unroll
            for (int nb = 0; nb < 2; ++nb) {
                const int row = wn * 32 + nb * 16 + lr;
                const int ch = kk * 2 + lc;
                const uint32_t off = (uint32_t)(row * 64 + ((ch ^ ((row >> 1) & 3)) * 16));
                ldsm4(bf[nb], buf + O1_B + off);
            }
#pragma unroll
            for (int mt = 0; mt < 4; ++mt)
#pragma unroll
                for (int nt = 0; nt < 4; ++nt) {
                    const int nb = nt >> 1, p = nt & 1;
                    mma16816(acc[mt][nt], ah[mt], bf[nb][p], bf[nb][p + 2]);
                }
#pragma unroll
            for (int mt = 0; mt < 4; ++mt)
#pragma unroll
                for (int nt = 0; nt < 4; ++nt) {
                    const int nb = nt >> 1, p = nt & 1;
                    mma16816(acc[mt][nt], al[mt], bf[nb][p], bf[nb][p + 2]);
                }
        }

        if (s < 30)
            fill1(sb + (uint32_t)((s + 2) % 3) * TS1, Ah, Al, B, m0, n0, (s + 2) * 32, tid);
        CP_COMMIT();
    }
    __syncthreads();

    // epilogue: e = exp(acc/32 + ct + qt + bqc); store e/16 fp16; column sums (f32)
    {
        const float bq = bqc[0];
        float* s_cp = (float*)sm;
        float cs[4][2];
#pragma unroll
        for (int nt = 0; nt < 4; ++nt) { cs[nt][0] = 0.f; cs[nt][1] = 0.f; }
#pragma unroll
        for (int mt = 0; mt < 4; ++mt) {
            const int row = m0 + wm * 64 + mt * 16 + g;
            const float ct0 = g_cterm[row], ct1 = g_cterm[row + 8];
#pragma unroll
            for (int nt = 0; nt < 4; ++nt) {
                const int col = n0 + wn * 32 + nt * 8 + tq * 2;
                const float q0 = g_qterm[col] + bq, q1 = g_qterm[col + 1] + bq;
                const float4 c = acc[mt][nt];
                const float e00 = __expf(c.x * 0.03125f + ct0 + q0);
                const float e01 = __expf(c.y * 0.03125f + ct0 + q1);
                const float e10 = __expf(c.z * 0.03125f + ct1 + q0);
                const float e11 = __expf(c.w * 0.03125f + ct1 + q1);
                const size_t o0 = (size_t)row * 1024 + col;
                const size_t o1 = (size_t)(row + 8) * 1024 + col;
                *(uint32_t*)((uint16_t*)g_e + o0) = h2_pack(e00 * 0.0625f, e01 * 0.0625f);
                *(uint32_t*)((uint16_t*)g_e + o1) = h2_pack(e10 * 0.0625f, e11 * 0.0625f);
                cs[nt][0] += e00 + e10;
                cs[nt][1] += e01 + e11;
            }
        }
#pragma unroll
        for (int nt = 0; nt < 4; ++nt)
#pragma unroll
            for (int o = 4; o < 32; o <<= 1) {
                cs[nt][0] += __shfl_xor_sync(0xffffffffu, cs[nt][0], o);
                cs[nt][1] += __shfl_xor_sync(0xffffffffu, cs[nt][1], o);
            }
        if (g == 0) {
#pragma unroll
            for (int nt = 0; nt < 4; ++nt) {
                const int col = wn * 32 + nt * 8 + tq * 2;
                s_cp[wm * 128 + col] = cs[nt][0];
                s_cp[wm * 128 + col + 1] = cs[nt][1];
            }
        }
        __syncthreads();
        if (tid < 128) {
            const float v = s_cp[tid] + s_cp[128 + tid];
            g_colpart[blockIdx.y * 1024 + n0 + tid] = v;
        }
    }
}

// -------- GEMM2: 3-stage cp.async, K=32/stage, 8 warps 64x32, 1 product -------
// stage = A(8K) | B(8K) = 16KB, 3 stages = 48KB
#define TS2   16384u
#define O2_B  8192u

__device__ __forceinline__ void fill2(uint32_t sbuf, const __half* A, const __half* B,
                                      int m0, int n0, int k0, int t) {
#pragma unroll
    for (int u = 0; u < 2; ++u) {
        const int row = (t >> 2) + u * 64, ch = t & 3;
        const int chs = ch ^ ((row >> 1) & 3);
        const uint32_t d = sbuf + (uint32_t)(row * 64 + chs * 16);
        const size_t oa = (size_t)(m0 + row) * 1024 + k0 + ch * 8;
        const size_t ob = (size_t)(n0 + row) * 1024 + k0 + ch * 8;
        CP_ASYNC(d,        A + oa);
        CP_ASYNC(d + O2_B, B + ob);
    }
}

__global__ __launch_bounds__(256, 2)
void k_mma2(const __half* __restrict__ A, const __half* __restrict__ B,
            float* __restrict__ out) {
    extern __shared__ char sm[];
    const uint32_t sb = smem_u32(sm);
    const int tid = threadIdx.x;
    const int lane = tid & 31, wid = tid >> 5;
    const int wm = wid & 1, wn = wid >> 1;
    const int g = lane >> 2, tq = lane & 3;
    const int m0 = blockIdx.y * 128, n0 = blockIdx.x * 128;
    const int lr = lane & 15, lc = lane >> 4;

    float4 acc[4][4];
#pragma unroll
    for (int i = 0; i < 4; ++i)
#pragma unroll
        for (int j = 0; j < 4; ++j) acc[i][j] = make_float4(0.f, 0.f, 0.f, 0.f);

    fill2(sb, A, B, m0, n0, 0, tid);        CP_COMMIT();
    fill2(sb + TS2, A, B, m0, n0, 32, tid); CP_COMMIT();

    for (int s = 0; s < 32; ++s) {
        CP_WAIT1();
        __syncthreads();
        const uint32_t buf = sb + (uint32_t)(s % 3) * TS2;

#pragma unroll
        for (int kk = 0; kk < 2; ++kk) {
            uint32_t af[4][4], bf[2][4];
#pragma unroll
            for (int mt = 0; mt < 4; ++mt) {
                const int row = wm * 64 + mt * 16 + lr;
                const int ch = kk * 2 + lc;
                const uint32_t off = (uint32_t)(row * 64 + ((ch ^ ((row >> 1) & 3)) * 16));
                ldsm4(af[mt], buf + off);
            }
#pragma unroll
            for (int nb = 0; nb < 2; ++nb) {
                const int row = wn * 32 + nb * 16 + lr;
                const int ch = kk * 2 + lc;
                const uint32_t off = (uint32_t)(row * 64 + ((ch ^ ((row >> 1) & 3)) * 16));
                ldsm4(bf[nb], buf + O2_B + off);
            }
#pragma unroll
            for (int mt = 0; mt < 4; ++mt)
#pragma unroll
                for (int nt = 0; nt < 4; ++nt) {
                    const int nb = nt >> 1, p = nt & 1;
                    mma16816(acc[mt][nt], af[mt], bf[nb][p], bf[nb][p + 2]);
                }
        }

        if (s < 30)
            fill2(sb + (uint32_t)((s + 2) % 3) * TS2, A, B, m0, n0, (s + 2) * 32, tid);
        CP_COMMIT();
    }
    __syncthreads();

#pragma unroll
    for (int mt = 0; mt < 4; ++mt) {
        const int row = m0 + wm * 64 + mt * 16 + g;
#pragma unroll
        for (int nt = 0; nt < 4; ++nt) {
            const int col = n0 + wn * 32 + nt * 8 + tq * 2;
            const float4 c = acc[mt][nt];
            *(float2*)(out + (size_t)row * 1024 + col) = make_float2(c.x, c.y);
            *(float2*)(out + (size_t)(row + 8) * 1024 + col) = make_float2(c.z, c.w);
        }
    }
}

// ---------------- Z_q reduction --------------------------------------------------
__global__ void k_colfin() {
    const int q = blockIdx.x * 64 + threadIdx.x;
    float s = 0.f;
#pragma unroll
    for (int i = 0; i < 64; ++i) s += g_colpart[i * 1024 + q];
    g_rz[q] = 1.f / s;
}

// ---------------- c2q softmax ---------------------------------------------------
__global__ void k_c2q() {
    const int t = threadIdx.x;
    const int lane = t & 31, wid = t >> 5;
    __shared__ float sred[32];
    __shared__ float sbc[2];
    float m = -1e30f;
    for (int c = t; c < C_LEN; c += 1024) m = fmaxf(m, g_bmax[c]);
#pragma unroll
    for (int o = 16; o; o >>= 1) m = fmaxf(m, __shfl_xor_sync(0xffffffffu, m, o));
    if (lane == 0) sred[wid] = m;
    __syncthreads();
    if (t < 32) {
        float v = sred[t];
#pragma unroll
        for (int o = 16; o; o >>= 1) v = fmaxf(v, __shfl_xor_sync(0xffffffffu, v, o));
        if (t == 0) sbc[0] = v;
    }
    __syncthreads();
    const float mm = sbc[0];
    float z = 0.f;
    for (int c = t; c < C_LEN; c += 1024) z += expf(g_bmax[c] - mm);
#pragma unroll
    for (int o = 16; o; o >>= 1) z += __shfl_xor_sync(0xffffffffu, z, o);
    __syncthreads();
    if (lane == 0) sred[wid] = z;
    __syncthreads();
    if (t < 32) {
        float v = sred[t];
#pragma unroll
        for (int o = 16; o; o >>= 1) v += __shfl_xor_sync(0xffffffffu, v, o);
        if (t == 0) sbc[1] = v;
    }
    __syncthreads();
    const float rz = 1.f / sbc[1];
    for (int c = t; c < C_LEN; c += 1024) g_w[c] = expf(g_bmax[c] - mm) * rz;
}

// ---------------- weighted column sum of H ---------------------------------------
__global__ void k_hpart(const float* __restrict__ H) {
    const int chunk = blockIdx.x, t = threadIdx.x;
    float a0 = 0.f, a1 = 0.f, a2 = 0.f, a3 = 0.f;
    const int c0 = chunk * 128;
    for (int c = c0; c < c0 + 128; ++c) {
        const float wv = g_w[c];
        const float* hr = H + (size_t)c * 1024;
        a0 = fmaf(wv, hr[t], a0);
        a1 = fmaf(wv, hr[t + 256], a1);
        a2 = fmaf(wv, hr[t + 512], a2);
        a3 = fmaf(wv, hr[t + 768], a3);
    }
    g_hpart[chunk][t] = a0;
    g_hpart[chunk][t + 256] = a1;
    g_hpart[chunk][t + 512] = a2;
    g_hpart[chunk][t + 768] = a3;
}

__global__ void k_hred() {
    const int d = blockIdx.x * 64 + threadIdx.x;
    float s = 0.f;
#pragma unroll
    for (int i = 0; i < 64; ++i) s += g_hpart[i][d];
    g_hrow[d] = s;
}

__global__ void k_bcast(float* __restrict__ out) {
    const float4 v = ((const float4*)g_hrow)[threadIdx.x];
    ((float4*)(out + (size_t)C_LEN * D_DIM))[blockIdx.x * 256 + threadIdx.x] = v;
}

// ---------------- launch ----------------------------------------------------------
extern "C" void kernel_launch(void* const* d_in, const int* in_sizes, int n_in,
                              void* d_out, int out_size) {
    const float* H   = (const float*)d_in[0];
    const float* U   = (const float*)d_in[1];
    const float* wq  = (const float*)d_in[2];
    const float* bq  = (const float*)d_in[3];
    const float* wc  = (const float*)d_in[4];
    const float* bc  = (const float*)d_in[5];
    const float* wqc = (const float*)d_in[6];
    const float* bqc = (const float*)d_in[7];
    float* out = (float*)d_out;

    static bool s_attr = false;
    if (!s_attr) {
        cudaFuncSetAttribute(k_mma1, cudaFuncAttributeMaxDynamicSharedMemorySize, 3 * TS1);
        cudaFuncSetAttribute(k_mma2, cudaFuncAttributeMaxDynamicSharedMemorySize, 3 * TS2);
        s_attr = true;
    }

    void *hh, *hl, *b1, *b2, *ee;
    cudaGetSymbolAddress(&hh, g_Hh);
    cudaGetSymbolAddress(&hl, g_Hl);
    cudaGetSymbolAddress(&b1, g_B1);
    cudaGetSymbolAddress(&b2, g_B2);
    cudaGetSymbolAddress(&ee, g_e);

    k_stats<<<C_LEN + Q_LEN, 256>>>(H, U, wq, bq, wc, bc, wqc);
    k_mma1<<<dim3(8, 64), 256, 3 * TS1>>>((const __half*)hh, (const __half*)hl,
                                          (const __half*)b1, bqc);
    k_colfin<<<16, 64>>>();
    k_prep_ut<<<dim3(32, 32), 256>>>(U);
    k_mma2<<<dim3(8, 64), 256, 3 * TS2>>>((const __half*)ee, (const __half*)b2, out);
    k_c2q<<<1, 1024>>>();
    k_hpart<<<64, 256>>>(H);
    k_hred<<<16, 64>>>();
    k_bcast<<<C_LEN, 256>>>(out);
}

// round 12
// speedup vs baseline: 2.5120x; 1.3445x over previous
#include <cuda_runtime.h>
#include <cuda_fp16.h>
#include <cstdint>
#include <math.h>

#define C_LEN 8192
#define Q_LEN 1024
#define D_DIM 1024

// ---------------- scratch (device globals) -----------------------------------
__device__ __align__(16) __half g_Hh[C_LEN * D_DIM];     // H (fp16 RN)
__device__ __align__(16) __half g_B1[Q_LEN * D_DIM];     // 32 * U * wqc (fp16 RN)
__device__ __align__(16) __half g_B2[D_DIM * Q_LEN];     // 16 * rz * U^T (fp16 RN)
__device__ __align__(16) __half g_e[C_LEN * Q_LEN];      // exp(s)/16 (fp16 RN)
__device__ __align__(16) float g_qterm[Q_LEN];
__device__ __align__(16) float g_cterm[C_LEN];
__device__ __align__(16) float g_bmax[C_LEN];
__device__ __align__(16) float g_colpart[64 * Q_LEN];
__device__ __align__(16) float g_rz[Q_LEN];
__device__ __align__(16) float g_w[C_LEN];
__device__ __align__(16) float g_hpart[128][D_DIM];
__device__ __align__(16) float g_hrow[D_DIM];

// ---------------- helpers -----------------------------------------------------
__device__ __forceinline__ uint32_t smem_u32(const void* p) {
    uint32_t a;
    asm("{ .reg .u64 t; cvta.to.shared.u64 t, %1; cvt.u32.u64 %0, t; }" : "=r"(a) : "l"(p));
    return a;
}
__device__ __forceinline__ void mma16816(float4& c, const uint32_t a[4],
                                         uint32_t b0, uint32_t b1) {
    asm volatile(
        "mma.sync.aligned.m16n8k16.row.col.f32.f16.f16.f32 "
        "{%0,%1,%2,%3}, {%4,%5,%6,%7}, {%8,%9}, {%0,%1,%2,%3};"
        : "+f"(c.x), "+f"(c.y), "+f"(c.z), "+f"(c.w)
        : "r"(a[0]), "r"(a[1]), "r"(a[2]), "r"(a[3]), "r"(b0), "r"(b1));
}
__device__ __forceinline__ void ldsm4(uint32_t d[4], uint32_t a) {
    asm volatile("ldmatrix.sync.aligned.m8n8.x4.shared.b16 {%0,%1,%2,%3}, [%4];"
                 : "=r"(d[0]), "=r"(d[1]), "=r"(d[2]), "=r"(d[3]) : "r"(a));
}
#define CP_ASYNC(d, s) asm volatile("cp.async.ca.shared.global [%0], [%1], 16;" :: "r"(d), "l"(s) : "memory")
#define CP_COMMIT()    asm volatile("cp.async.commit_group;" ::: "memory")
#define CP_WAIT1()     asm volatile("cp.async.wait_group 1;" ::: "memory")

__device__ __forceinline__ uint32_t h2_pack(float a, float b) {
    __half2 h = __floats2half2_rn(a, b);
    return *(uint32_t*)&h;
}

// ------ fused stats+split: blocks 0..8191 -> H row, 8192..9215 -> U row --------
__global__ void k_stats(const float* __restrict__ H, const float* __restrict__ U,
                        const float* __restrict__ wq, const float* __restrict__ bq,
                        const float* __restrict__ wc, const float* __restrict__ bc,
                        const float* __restrict__ wqc) {
    const int t = threadIdx.x;
    __shared__ float sp[8], sm2[8];
    if (blockIdx.x < C_LEN) {
        const int c = blockIdx.x;
        const int i = c * 1024 + t * 4;
        float4 h = *(const float4*)(H + i);
        float4 w = ((const float4*)wc)[t];
        *(uint2*)((uint16_t*)g_Hh + i) = make_uint2(h2_pack(h.x, h.y), h2_pack(h.z, h.w));
        float p = h.x * w.x + h.y * w.y + h.z * w.z + h.w * w.w;
        float m = fmaxf(fmaxf(h.x, h.y), fmaxf(h.z, h.w));
#pragma unroll
        for (int o = 16; o; o >>= 1) {
            p += __shfl_down_sync(0xffffffffu, p, o);
            m = fmaxf(m, __shfl_down_sync(0xffffffffu, m, o));
        }
        if ((t & 31) == 0) { sp[t >> 5] = p; sm2[t >> 5] = m; }
        __syncthreads();
        if (t == 0) {
            float pp = sp[0], mm = sm2[0];
#pragma unroll
            for (int i2 = 1; i2 < 8; ++i2) { pp += sp[i2]; mm = fmaxf(mm, sm2[i2]); }
            g_cterm[c] = pp + bc[0];
            g_bmax[c] = mm;
        }
    } else {
        const int n = blockIdx.x - C_LEN;
        const int i = n * 1024 + t * 4;
        float4 u = *(const float4*)(U + i);
        float4 w = ((const float4*)wq)[t];
        float p = u.x * w.x + u.y * w.y + u.z * w.z + u.w * w.w;
        float4 wq2 = ((const float4*)wqc)[t];
        *(uint2*)((uint16_t*)g_B1 + i) =
            make_uint2(h2_pack(32.f * u.x * wq2.x, 32.f * u.y * wq2.y),
                       h2_pack(32.f * u.z * wq2.z, 32.f * u.w * wq2.w));
#pragma unroll
        for (int o = 16; o; o >>= 1) p += __shfl_down_sync(0xffffffffu, p, o);
        if ((t & 31) == 0) sp[t >> 5] = p;
        __syncthreads();
        if (t == 0) {
            float s = sp[0];
#pragma unroll
            for (int i2 = 1; i2 < 8; ++i2) s += sp[i2];
            g_qterm[n] = s + bq[0];
        }
    }
}

// ---------------- prep: transpose B2 = 16 * rz * U^T ---------------------------
__global__ void k_prep_ut(const float* __restrict__ U) {
    __shared__ float t[32][33];
    const int tx = threadIdx.x & 31, ty = threadIdx.x >> 5;
    const int d0 = blockIdx.x * 32, q0 = blockIdx.y * 32;
#pragma unroll
    for (int i = 0; i < 4; ++i)
        t[ty + 8 * i][tx] = U[(size_t)(q0 + ty + 8 * i) * 1024 + d0 + tx];
    __syncthreads();
#pragma unroll
    for (int i = 0; i < 4; ++i) {
        const int d = d0 + ty + 8 * i;
        const int q = q0 + tx;
        const float v = t[tx][ty + 8 * i] * g_rz[q] * 16.f;
        ((__half*)g_B2)[(size_t)d * 1024 + q] = __float2half_rn(v);
    }
}

// -------- GEMM: 3-stage cp.async, K=32/stage, 8 warps 64x32, 1 product --------
// stage = A(8K) | B(8K) = 16KB, 3 stages = 48KB, 2 CTA/SM
#define TS    16384u
#define O_B   8192u

__device__ __forceinline__ void fill_st(uint32_t sbuf, const __half* A, const __half* B,
                                        int m0, int n0, int k0, int t) {
#pragma unroll
    for (int u = 0; u < 2; ++u) {
        const int row = (t >> 2) + u * 64, ch = t & 3;
        const int chs = ch ^ ((row >> 1) & 3);
        const uint32_t d = sbuf + (uint32_t)(row * 64 + chs * 16);
        const size_t oa = (size_t)(m0 + row) * 1024 + k0 + ch * 8;
        const size_t ob = (size_t)(n0 + row) * 1024 + k0 + ch * 8;
        CP_ASYNC(d,       A + oa);
        CP_ASYNC(d + O_B, B + ob);
    }
}

// PASS=1: acc=32*s -> e=exp(s+..)/16 fp16 + col sums.  PASS=2: store fp32 out.
template <int PASS>
__global__ __launch_bounds__(256, 2)
void k_mma(const __half* __restrict__ A, const __half* __restrict__ B,
           const float* __restrict__ bqc, float* __restrict__ out) {
    extern __shared__ char sm[];
    const uint32_t sb = smem_u32(sm);
    const int tid = threadIdx.x;
    const int lane = tid & 31, wid = tid >> 5;
    const int wm = wid & 1, wn = wid >> 1;
    const int g = lane >> 2, tq = lane & 3;
    const int m0 = blockIdx.y * 128, n0 = blockIdx.x * 128;
    const int lr = lane & 15, lc = lane >> 4;

    float4 acc[4][4];
#pragma unroll
    for (int i = 0; i < 4; ++i)
#pragma unroll
        for (int j = 0; j < 4; ++j) acc[i][j] = make_float4(0.f, 0.f, 0.f, 0.f);

    fill_st(sb, A, B, m0, n0, 0, tid);       CP_COMMIT();
    fill_st(sb + TS, A, B, m0, n0, 32, tid); CP_COMMIT();

    for (int s = 0; s < 32; ++s) {
        CP_WAIT1();
        __syncthreads();
        const uint32_t buf = sb + (uint32_t)(s % 3) * TS;

#pragma unroll
        for (int kk = 0; kk < 2; ++kk) {
            uint32_t af[4][4], bf[2][4];
#pragma unroll
            for (int mt = 0; mt < 4; ++mt) {
                const int row = wm * 64 + mt * 16 + lr;
                const int ch = kk * 2 + lc;
                const uint32_t off = (uint32_t)(row * 64 + ((ch ^ ((row >> 1) & 3)) * 16));
                ldsm4(af[mt], buf + off);
            }
#pragma unroll
            for (int nb = 0; nb < 2; ++nb) {
                const int row = wn * 32 + nb * 16 + lr;
                const int ch = kk * 2 + lc;
                const uint32_t off = (uint32_t)(row * 64 + ((ch ^ ((row >> 1) & 3)) * 16));
                ldsm4(bf[nb], buf + O_B + off);
            }
#pragma unroll
            for (int mt = 0; mt < 4; ++mt)
#pragma unroll
                for (int nt = 0; nt < 4; ++nt) {
                    const int nb = nt >> 1, p = nt & 1;
                    mma16816(acc[mt][nt], af[mt], bf[nb][p], bf[nb][p + 2]);
                }
        }

        if (s < 30)
            fill_st(sb + (uint32_t)((s + 2) % 3) * TS, A, B, m0, n0, (s + 2) * 32, tid);
        CP_COMMIT();
    }
    __syncthreads();

    if (PASS == 1) {
        const float bq = bqc[0];
        float* s_cp = (float*)sm;
        float cs[4][2];
#pragma unroll
        for (int nt = 0; nt < 4; ++nt) { cs[nt][0] = 0.f; cs[nt][1] = 0.f; }
#pragma unroll
        for (int mt = 0; mt < 4; ++mt) {
            const int row = m0 + wm * 64 + mt * 16 + g;
            const float ct0 = g_cterm[row], ct1 = g_cterm[row + 8];
#pragma unroll
            for (int nt = 0; nt < 4; ++nt) {
                const int col = n0 + wn * 32 + nt * 8 + tq * 2;
                const float q0 = g_qterm[col] + bq, q1 = g_qterm[col + 1] + bq;
                const float4 c = acc[mt][nt];
                const float e00 = __expf(c.x * 0.03125f + ct0 + q0);
                const float e01 = __expf(c.y * 0.03125f + ct0 + q1);
                const float e10 = __expf(c.z * 0.03125f + ct1 + q0);
                const float e11 = __expf(c.w * 0.03125f + ct1 + q1);
                const size_t o0 = (size_t)row * 1024 + col;
                const size_t o1 = (size_t)(row + 8) * 1024 + col;
                *(uint32_t*)((uint16_t*)g_e + o0) = h2_pack(e00 * 0.0625f, e01 * 0.0625f);
                *(uint32_t*)((uint16_t*)g_e + o1) = h2_pack(e10 * 0.0625f, e11 * 0.0625f);
                cs[nt][0] += e00 + e10;
                cs[nt][1] += e01 + e11;
            }
        }
#pragma unroll
        for (int nt = 0; nt < 4; ++nt)
#pragma unroll
            for (int o = 4; o < 32; o <<= 1) {
                cs[nt][0] += __shfl_xor_sync(0xffffffffu, cs[nt][0], o);
                cs[nt][1] += __shfl_xor_sync(0xffffffffu, cs[nt][1], o);
            }
        if (g == 0) {
#pragma unroll
            for (int nt = 0; nt < 4; ++nt) {
                const int col = wn * 32 + nt * 8 + tq * 2;
                s_cp[wm * 128 + col] = cs[nt][0];
                s_cp[wm * 128 + col + 1] = cs[nt][1];
            }
        }
        __syncthreads();
        if (tid < 128) {
            const float v = s_cp[tid] + s_cp[128 + tid];
            g_colpart[blockIdx.y * 1024 + n0 + tid] = v;
        }
    } else {
#pragma unroll
        for (int mt = 0; mt < 4; ++mt) {
            const int row = m0 + wm * 64 + mt * 16 + g;
#pragma unroll
            for (int nt = 0; nt < 4; ++nt) {
                const int col = n0 + wn * 32 + nt * 8 + tq * 2;
                const float4 c = acc[mt][nt];
                *(float2*)(out + (size_t)row * 1024 + col) = make_float2(c.x, c.y);
                *(float2*)(out + (size_t)(row + 8) * 1024 + col) = make_float2(c.z, c.w);
            }
        }
    }
}

// ---------------- Z_q reduction --------------------------------------------------
__global__ void k_colfin() {
    const int q = blockIdx.x * 64 + threadIdx.x;
    float s = 0.f;
#pragma unroll
    for (int i = 0; i < 64; ++i) s += g_colpart[i * 1024 + q];
    g_rz[q] = 1.f / s;
}

// ---------------- c2q softmax ---------------------------------------------------
__global__ void k_c2q() {
    const int t = threadIdx.x;
    const int lane = t & 31, wid = t >> 5;
    __shared__ float sred[32];
    __shared__ float sbc[2];
    float m = -1e30f;
    for (int c = t; c < C_LEN; c += 1024) m = fmaxf(m, g_bmax[c]);
#pragma unroll
    for (int o = 16; o; o >>= 1) m = fmaxf(m, __shfl_xor_sync(0xffffffffu, m, o));
    if (lane == 0) sred[wid] = m;
    __syncthreads();
    if (t < 32) {
        float v = sred[t];
#pragma unroll
        for (int o = 16; o; o >>= 1) v = fmaxf(v, __shfl_xor_sync(0xffffffffu, v, o));
        if (t == 0) sbc[0] = v;
    }
    __syncthreads();
    const float mm = sbc[0];
    float z = 0.f;
    for (int c = t; c < C_LEN; c += 1024) z += expf(g_bmax[c] - mm);
#pragma unroll
    for (int o = 16; o; o >>= 1) z += __shfl_xor_sync(0xffffffffu, z, o);
    __syncthreads();
    if (lane == 0) sred[wid] = z;
    __syncthreads();
    if (t < 32) {
        float v = sred[t];
#pragma unroll
        for (int o = 16; o; o >>= 1) v += __shfl_xor_sync(0xffffffffu, v, o);
        if (t == 0) sbc[1] = v;
    }
    __syncthreads();
    const float rz = 1.f / sbc[1];
    for (int c = t; c < C_LEN; c += 1024) g_w[c] = expf(g_bmax[c] - mm) * rz;
}

// ---------------- weighted column sum of H (128 chunks of 64 rows) ---------------
__global__ void k_hpart(const float* __restrict__ H) {
    const int chunk = blockIdx.x, t = threadIdx.x;
    float a0 = 0.f, a1 = 0.f, a2 = 0.f, a3 = 0.f;
    const int c0 = chunk * 64;
    for (int c = c0; c < c0 + 64; ++c) {
        const float wv = g_w[c];
        const float* hr = H + (size_t)c * 1024;
        a0 = fmaf(wv, hr[t], a0);
        a1 = fmaf(wv, hr[t + 256], a1);
        a2 = fmaf(wv, hr[t + 512], a2);
        a3 = fmaf(wv, hr[t + 768], a3);
    }
    g_hpart[chunk][t] = a0;
    g_hpart[chunk][t + 256] = a1;
    g_hpart[chunk][t + 512] = a2;
    g_hpart[chunk][t + 768] = a3;
}

__global__ void k_hred() {
    const int d = blockIdx.x * 64 + threadIdx.x;
    float s = 0.f;
#pragma unroll
    for (int i = 0; i < 128; ++i) s += g_hpart[i][d];
    g_hrow[d] = s;
}

__global__ void k_bcast(float* __restrict__ out) {
    const float4 v = ((const float4*)g_hrow)[threadIdx.x];
    ((float4*)(out + (size_t)C_LEN * D_DIM))[blockIdx.x * 256 + threadIdx.x] = v;
}

// ---------------- launch ----------------------------------------------------------
extern "C" void kernel_launch(void* const* d_in, const int* in_sizes, int n_in,
                              void* d_out, int out_size) {
    const float* H   = (const float*)d_in[0];
    const float* U   = (const float*)d_in[1];
    const float* wq  = (const float*)d_in[2];
    const float* bq  = (const float*)d_in[3];
    const float* wc  = (const float*)d_in[4];
    const float* bc  = (const float*)d_in[5];
    const float* wqc = (const float*)d_in[6];
    const float* bqc = (const float*)d_in[7];
    float* out = (float*)d_out;

    static bool s_attr = false;
    if (!s_attr) {
        cudaFuncSetAttribute(k_mma<1>, cudaFuncAttributeMaxDynamicSharedMemorySize, 3 * TS);
        cudaFuncSetAttribute(k_mma<2>, cudaFuncAttributeMaxDynamicSharedMemorySize, 3 * TS);
        s_attr = true;
    }

    void *hh, *b1, *b2, *ee;
    cudaGetSymbolAddress(&hh, g_Hh);
    cudaGetSymbolAddress(&b1, g_B1);
    cudaGetSymbolAddress(&b2, g_B2);
    cudaGetSymbolAddress(&ee, g_e);

    k_stats<<<C_LEN + Q_LEN, 256>>>(H, U, wq, bq, wc, bc, wqc);
    k_mma<1><<<dim3(8, 64), 256, 3 * TS>>>((const __half*)hh, (const __half*)b1, bqc, nullptr);
    k_colfin<<<16, 64>>>();
    k_prep_ut<<<dim3(32, 32), 256>>>(U);
    k_mma<2><<<dim3(8, 64), 256, 3 * TS>>>((const __half*)ee, (const __half*)b2, bqc, out);
    k_c2q<<<1, 1024>>>();
    k_hpart<<<128, 256>>>(H);
    k_hred<<<16, 64>>>();
    k_bcast<<<C_LEN, 256>>>(out);
}

// round 13
// speedup vs baseline: 2.5981x; 1.0343x over previous
#include <cuda_runtime.h>
#include <cuda_fp16.h>
#include <cstdint>
#include <math.h>

#define C_LEN 8192
#define Q_LEN 1024
#define D_DIM 1024

// ---------------- scratch (device globals) -----------------------------------
__device__ __align__(16) __half g_Hh[C_LEN * D_DIM];     // H (fp16 RN)
__device__ __align__(16) __half g_B1[Q_LEN * D_DIM];     // 32 * U * wqc (fp16 RN)
__device__ __align__(16) __half g_B2[D_DIM * Q_LEN];     // 16 * rz * U^T (fp16 RN)
__device__ __align__(16) __half g_e[C_LEN * Q_LEN];      // exp(s)/16 (fp16 RN)
__device__ __align__(16) float g_qterm[Q_LEN];
__device__ __align__(16) float g_cterm[C_LEN];
__device__ __align__(16) float g_bmax[C_LEN];
__device__ __align__(16) float g_colpart[64 * Q_LEN];
__device__ __align__(16) float g_w[C_LEN];
__device__ __align__(16) float g_hpart[128][D_DIM];
__device__ __align__(16) float g_hrow[D_DIM];

// ---------------- helpers -----------------------------------------------------
__device__ __forceinline__ uint32_t smem_u32(const void* p) {
    uint32_t a;
    asm("{ .reg .u64 t; cvta.to.shared.u64 t, %1; cvt.u32.u64 %0, t; }" : "=r"(a) : "l"(p));
    return a;
}
__device__ __forceinline__ void mma16816(float4& c, const uint32_t a[4],
                                         uint32_t b0, uint32_t b1) {
    asm volatile(
        "mma.sync.aligned.m16n8k16.row.col.f32.f16.f16.f32 "
        "{%0,%1,%2,%3}, {%4,%5,%6,%7}, {%8,%9}, {%0,%1,%2,%3};"
        : "+f"(c.x), "+f"(c.y), "+f"(c.z), "+f"(c.w)
        : "r"(a[0]), "r"(a[1]), "r"(a[2]), "r"(a[3]), "r"(b0), "r"(b1));
}
__device__ __forceinline__ void ldsm4(uint32_t d[4], uint32_t a) {
    asm volatile("ldmatrix.sync.aligned.m8n8.x4.shared.b16 {%0,%1,%2,%3}, [%4];"
                 : "=r"(d[0]), "=r"(d[1]), "=r"(d[2]), "=r"(d[3]) : "r"(a));
}
#define CP_ASYNC(d, s) asm volatile("cp.async.ca.shared.global [%0], [%1], 16;" :: "r"(d), "l"(s) : "memory")
#define CP_COMMIT()    asm volatile("cp.async.commit_group;" ::: "memory")
#define CP_WAIT1()     asm volatile("cp.async.wait_group 1;" ::: "memory")

__device__ __forceinline__ uint32_t h2_pack(float a, float b) {
    __half2 h = __floats2half2_rn(a, b);
    return *(uint32_t*)&h;
}

// ------ fused stats+split: blocks 0..8191 -> H row, 8192..9215 -> U row --------
__global__ void k_stats(const float* __restrict__ H, const float* __restrict__ U,
                        const float* __restrict__ wq, const float* __restrict__ bq,
                        const float* __restrict__ wc, const float* __restrict__ bc,
                        const float* __restrict__ wqc) {
    const int t = threadIdx.x;
    __shared__ float sp[8], sm2[8];
    if (blockIdx.x < C_LEN) {
        const int c = blockIdx.x;
        const int i = c * 1024 + t * 4;
        float4 h = *(const float4*)(H + i);
        float4 w = ((const float4*)wc)[t];
        *(uint2*)((uint16_t*)g_Hh + i) = make_uint2(h2_pack(h.x, h.y), h2_pack(h.z, h.w));
        float p = h.x * w.x + h.y * w.y + h.z * w.z + h.w * w.w;
        float m = fmaxf(fmaxf(h.x, h.y), fmaxf(h.z, h.w));
#pragma unroll
        for (int o = 16; o; o >>= 1) {
            p += __shfl_down_sync(0xffffffffu, p, o);
            m = fmaxf(m, __shfl_down_sync(0xffffffffu, m, o));
        }
        if ((t & 31) == 0) { sp[t >> 5] = p; sm2[t >> 5] = m; }
        __syncthreads();
        if (t == 0) {
            float pp = sp[0], mm = sm2[0];
#pragma unroll
            for (int i2 = 1; i2 < 8; ++i2) { pp += sp[i2]; mm = fmaxf(mm, sm2[i2]); }
            g_cterm[c] = pp + bc[0];
            g_bmax[c] = mm;
        }
    } else {
        const int n = blockIdx.x - C_LEN;
        const int i = n * 1024 + t * 4;
        float4 u = *(const float4*)(U + i);
        float4 w = ((const float4*)wq)[t];
        float p = u.x * w.x + u.y * w.y + u.z * w.z + u.w * w.w;
        float4 wq2 = ((const float4*)wqc)[t];
        *(uint2*)((uint16_t*)g_B1 + i) =
            make_uint2(h2_pack(32.f * u.x * wq2.x, 32.f * u.y * wq2.y),
                       h2_pack(32.f * u.z * wq2.z, 32.f * u.w * wq2.w));
#pragma unroll
        for (int o = 16; o; o >>= 1) p += __shfl_down_sync(0xffffffffu, p, o);
        if ((t & 31) == 0) sp[t >> 5] = p;
        __syncthreads();
        if (t == 0) {
            float s = sp[0];
#pragma unroll
            for (int i2 = 1; i2 < 8; ++i2) s += sp[i2];
            g_qterm[n] = s + bq[0];
        }
    }
}

// ------- prep: Z_q reduction + transpose B2 = 16 * rz * U^T (fused) ------------
__global__ void k_prep_ut(const float* __restrict__ U) {
    __shared__ float t[32][33];
    __shared__ float srz[32];
    const int tid = threadIdx.x;
    const int tx = tid & 31, ty = tid >> 5;
    const int d0 = blockIdx.x * 32, q0 = blockIdx.y * 32;
    if (tid < 32) {
        float s = 0.f;
#pragma unroll
        for (int i = 0; i < 64; ++i) s += g_colpart[i * 1024 + q0 + tid];
        srz[tid] = 16.f / s;
    }
#pragma unroll
    for (int i = 0; i < 4; ++i)
        t[ty + 8 * i][tx] = U[(size_t)(q0 + ty + 8 * i) * 1024 + d0 + tx];
    __syncthreads();
#pragma unroll
    for (int i = 0; i < 4; ++i) {
        const int d = d0 + ty + 8 * i;
        const float v = t[tx][ty + 8 * i] * srz[tx];
        ((__half*)g_B2)[(size_t)d * 1024 + q0 + tx] = __float2half_rn(v);
    }
}

// -------- GEMM: 3-stage cp.async, K=32/stage, 8 warps 64x32, 1 product --------
#define TS    16384u
#define O_B   8192u

__device__ __forceinline__ void fill_st(uint32_t sbuf, const __half* A, const __half* B,
                                        int m0, int n0, int k0, int t) {
#pragma unroll
    for (int u = 0; u < 2; ++u) {
        const int row = (t >> 2) + u * 64, ch = t & 3;
        const int chs = ch ^ ((row >> 1) & 3);
        const uint32_t d = sbuf + (uint32_t)(row * 64 + chs * 16);
        const size_t oa = (size_t)(m0 + row) * 1024 + k0 + ch * 8;
        const size_t ob = (size_t)(n0 + row) * 1024 + k0 + ch * 8;
        CP_ASYNC(d,       A + oa);
        CP_ASYNC(d + O_B, B + ob);
    }
}

// PASS=1: acc=32*s -> e=exp(s+..)/16 fp16 + col sums.
// PASS=2: store U_toggler fp32 + broadcast H_toggler slice.
template <int PASS>
__global__ __launch_bounds__(256, 2)
void k_mma(const __half* __restrict__ A, const __half* __restrict__ B,
           const float* __restrict__ bqc, float* __restrict__ out) {
    extern __shared__ char sm[];
    const uint32_t sb = smem_u32(sm);
    const int tid = threadIdx.x;
    const int lane = tid & 31, wid = tid >> 5;
    const int wm = wid & 1, wn = wid >> 1;
    const int g = lane >> 2, tq = lane & 3;
    const int m0 = blockIdx.y * 128, n0 = blockIdx.x * 128;
    const int lr = lane & 15, lc = lane >> 4;

    float4 acc[4][4];
#pragma unroll
    for (int i = 0; i < 4; ++i)
#pragma unroll
        for (int j = 0; j < 4; ++j) acc[i][j] = make_float4(0.f, 0.f, 0.f, 0.f);

    fill_st(sb, A, B, m0, n0, 0, tid);       CP_COMMIT();
    fill_st(sb + TS, A, B, m0, n0, 32, tid); CP_COMMIT();

    for (int s = 0; s < 32; ++s) {
        CP_WAIT1();
        __syncthreads();
        const uint32_t buf = sb + (uint32_t)(s % 3) * TS;

#pragma unroll
        for (int kk = 0; kk < 2; ++kk) {
            uint32_t af[4][4], bf[2][4];
#pragma unroll
            for (int mt = 0; mt < 4; ++mt) {
                const int row = wm * 64 + mt * 16 + lr;
                const int ch = kk * 2 + lc;
                const uint32_t off = (uint32_t)(row * 64 + ((ch ^ ((row >> 1) & 3)) * 16));
                ldsm4(af[mt], buf + off);
            }
#pragma unroll
            for (int nb = 0; nb < 2; ++nb) {
                const int row = wn * 32 + nb * 16 + lr;
                const int ch = kk * 2 + lc;
                const uint32_t off = (uint32_t)(row * 64 + ((ch ^ ((row >> 1) & 3)) * 16));
                ldsm4(bf[nb], buf + O_B + off);
            }
#pragma unroll
            for (int mt = 0; mt < 4; ++mt)
#pragma unroll
                for (int nt = 0; nt < 4; ++nt) {
                    const int nb = nt >> 1, p = nt & 1;
                    mma16816(acc[mt][nt], af[mt], bf[nb][p], bf[nb][p + 2]);
                }
        }

        if (s < 30)
            fill_st(sb + (uint32_t)((s + 2) % 3) * TS, A, B, m0, n0, (s + 2) * 32, tid);
        CP_COMMIT();
    }
    __syncthreads();

    if (PASS == 1) {
        const float bq = bqc[0];
        float* s_cp = (float*)sm;
        float cs[4][2];
#pragma unroll
        for (int nt = 0; nt < 4; ++nt) { cs[nt][0] = 0.f; cs[nt][1] = 0.f; }
#pragma unroll
        for (int mt = 0; mt < 4; ++mt) {
            const int row = m0 + wm * 64 + mt * 16 + g;
            const float ct0 = g_cterm[row], ct1 = g_cterm[row + 8];
#pragma unroll
            for (int nt = 0; nt < 4; ++nt) {
                const int col = n0 + wn * 32 + nt * 8 + tq * 2;
                const float q0 = g_qterm[col] + bq, q1 = g_qterm[col + 1] + bq;
                const float4 c = acc[mt][nt];
                const float e00 = __expf(c.x * 0.03125f + ct0 + q0);
                const float e01 = __expf(c.y * 0.03125f + ct0 + q1);
                const float e10 = __expf(c.z * 0.03125f + ct1 + q0);
                const float e11 = __expf(c.w * 0.03125f + ct1 + q1);
                const size_t o0 = (size_t)row * 1024 + col;
                const size_t o1 = (size_t)(row + 8) * 1024 + col;
                *(uint32_t*)((uint16_t*)g_e + o0) = h2_pack(e00 * 0.0625f, e01 * 0.0625f);
                *(uint32_t*)((uint16_t*)g_e + o1) = h2_pack(e10 * 0.0625f, e11 * 0.0625f);
                cs[nt][0] += e00 + e10;
                cs[nt][1] += e01 + e11;
            }
        }
#pragma unroll
        for (int nt = 0; nt < 4; ++nt)
#pragma unroll
            for (int o = 4; o < 32; o <<= 1) {
                cs[nt][0] += __shfl_xor_sync(0xffffffffu, cs[nt][0], o);
                cs[nt][1] += __shfl_xor_sync(0xffffffffu, cs[nt][1], o);
            }
        if (g == 0) {
#pragma unroll
            for (int nt = 0; nt < 4; ++nt) {
                const int col = wn * 32 + nt * 8 + tq * 2;
                s_cp[wm * 128 + col] = cs[nt][0];
                s_cp[wm * 128 + col + 1] = cs[nt][1];
            }
        }
        __syncthreads();
        if (tid < 128) {
            const float v = s_cp[tid] + s_cp[128 + tid];
            g_colpart[blockIdx.y * 1024 + n0 + tid] = v;
        }
    } else {
#pragma unroll
        for (int mt = 0; mt < 4; ++mt) {
            const int row = m0 + wm * 64 + mt * 16 + g;
#pragma unroll
            for (int nt = 0; nt < 4; ++nt) {
                const int col = n0 + wn * 32 + nt * 8 + tq * 2;
                const float4 c = acc[mt][nt];
                *(float2*)(out + (size_t)row * 1024 + col) = make_float2(c.x, c.y);
                *(float2*)(out + (size_t)(row + 8) * 1024 + col) = make_float2(c.z, c.w);
            }
        }
        // fused H_toggler broadcast: rows m0..m0+128, cols n0..n0+128
        const float4 hv = *(const float4*)(g_hrow + n0 + (tid & 31) * 4);
        float* o2 = out + (size_t)C_LEN * 1024;
#pragma unroll
        for (int r = tid >> 5; r < 128; r += 8)
            *(float4*)(o2 + (size_t)(m0 + r) * 1024 + n0 + (tid & 31) * 4) = hv;
    }
}

// ---------------- c2q softmax ---------------------------------------------------
__global__ void k_c2q() {
    const int t = threadIdx.x;
    const int lane = t & 31, wid = t >> 5;
    __shared__ float sred[32];
    __shared__ float sbc[2];
    float m = -1e30f;
    for (int c = t; c < C_LEN; c += 1024) m = fmaxf(m, g_bmax[c]);
#pragma unroll
    for (int o = 16; o; o >>= 1) m = fmaxf(m, __shfl_xor_sync(0xffffffffu, m, o));
    if (lane == 0) sred[wid] = m;
    __syncthreads();
    if (t < 32) {
        float v = sred[t];
#pragma unroll
        for (int o = 16; o; o >>= 1) v = fmaxf(v, __shfl_xor_sync(0xffffffffu, v, o));
        if (t == 0) sbc[0] = v;
    }
    __syncthreads();
    const float mm = sbc[0];
    float z = 0.f;
    for (int c = t; c < C_LEN; c += 1024) z += expf(g_bmax[c] - mm);
#pragma unroll
    for (int o = 16; o; o >>= 1) z += __shfl_xor_sync(0xffffffffu, z, o);
    __syncthreads();
    if (lane == 0) sred[wid] = z;
    __syncthreads();
    if (t < 32) {
        float v = sred[t];
#pragma unroll
        for (int o = 16; o; o >>= 1) v += __shfl_xor_sync(0xffffffffu, v, o);
        if (t == 0) sbc[1] = v;
    }
    __syncthreads();
    const float rz = 1.f / sbc[1];
    for (int c = t; c < C_LEN; c += 1024) g_w[c] = expf(g_bmax[c] - mm) * rz;
}

// ---------------- weighted column sum of H (128 chunks of 64 rows) ---------------
__global__ void k_hpart(const float* __restrict__ H) {
    const int chunk = blockIdx.x, t = threadIdx.x;
    float a0 = 0.f, a1 = 0.f, a2 = 0.f, a3 = 0.f;
    const int c0 = chunk * 64;
    for (int c = c0; c < c0 + 64; ++c) {
        const float wv = g_w[c];
        const float* hr = H + (size_t)c * 1024;
        a0 = fmaf(wv, hr[t], a0);
        a1 = fmaf(wv, hr[t + 256], a1);
        a2 = fmaf(wv, hr[t + 512], a2);
        a3 = fmaf(wv, hr[t + 768], a3);
    }
    g_hpart[chunk][t] = a0;
    g_hpart[chunk][t + 256] = a1;
    g_hpart[chunk][t + 512] = a2;
    g_hpart[chunk][t + 768] = a3;
}

__global__ void k_hred() {
    const int d = blockIdx.x * 64 + threadIdx.x;
    float s = 0.f;
#pragma unroll
    for (int i = 0; i < 128; ++i) s += g_hpart[i][d];
    g_hrow[d] = s;
}

// ---------------- launch ----------------------------------------------------------
extern "C" void kernel_launch(void* const* d_in, const int* in_sizes, int n_in,
                              void* d_out, int out_size) {
    const float* H   = (const float*)d_in[0];
    const float* U   = (const float*)d_in[1];
    const float* wq  = (const float*)d_in[2];
    const float* bq  = (const float*)d_in[3];
    const float* wc  = (const float*)d_in[4];
    const float* bc  = (const float*)d_in[5];
    const float* wqc = (const float*)d_in[6];
    const float* bqc = (const float*)d_in[7];
    float* out = (float*)d_out;

    static bool s_attr = false;
    if (!s_attr) {
        cudaFuncSetAttribute(k_mma<1>, cudaFuncAttributeMaxDynamicSharedMemorySize, 3 * TS);
        cudaFuncSetAttribute(k_mma<2>, cudaFuncAttributeMaxDynamicSharedMemorySize, 3 * TS);
        s_attr = true;
    }

    void *hh, *b1, *b2, *ee;
    cudaGetSymbolAddress(&hh, g_Hh);
    cudaGetSymbolAddress(&b1, g_B1);
    cudaGetSymbolAddress(&b2, g_B2);
    cudaGetSymbolAddress(&ee, g_e);

    k_stats<<<C_LEN + Q_LEN, 256>>>(H, U, wq, bq, wc, bc, wqc);
    k_mma<1><<<dim3(8, 64), 256, 3 * TS>>>((const __half*)hh, (const __half*)b1, bqc, nullptr);
    k_prep_ut<<<dim3(32, 32), 256>>>(U);
    k_c2q<<<1, 1024>>>();
    k_hpart<<<128, 256>>>(H);
    k_hred<<<16, 64>>>();
    k_mma<2><<<dim3(8, 64), 256, 3 * TS>>>((const __half*)ee, (const __half*)b2, bqc, out);
}